// round 1
// baseline (speedup 1.0000x reference)
#include <cuda_runtime.h>
#include <cuda_bf16.h>
#include <cstdint>
#include <cstddef>

typedef __nv_bfloat16 bf16;

#define T_ 256
#define B_ 64
#define D_ 512
#define H_ 1024
#define G_ 4096
#define TB_ (T_ * B_)
#define OUTS_ (TB_ * H_)   // 16777216

// ---------------- device scratch (allocation-free) ----------------
__device__ bf16  g_Xp  [(size_t)TB_ * (2 * D_)];   // input packed [hi|lo], row stride 1024
__device__ bf16  g_Wi0p[(size_t)G_  * (2 * D_)];   // row stride 1024 (perm rows)
__device__ bf16  g_Wh0p[(size_t)G_  * (2 * H_)];   // row stride 2048
__device__ bf16  g_Wi1p[(size_t)G_  * (2 * H_)];
__device__ bf16  g_Wh1p[(size_t)G_  * (2 * H_)];
__device__ float g_b0[G_], g_b1[G_];               // permuted bias sums
__device__ float g_G0[(size_t)TB_ * G_];           // precomputed x@Wi0^T + b (permuted cols)
__device__ float g_h[2 * B_ * H_], g_c[2 * B_ * H_];   // [layer][b][j]
__device__ bf16  g_h0p[2][B_ * 2 * H_];            // ping-pong packed h, row stride 2048
__device__ bf16  g_x1p[2][B_ * 2 * H_];
__device__ bf16  g_h1p[2][B_ * 2 * H_];

// ---------------- packing ----------------
// dst layout per row r: [hi(0..K-1) | lo(0..K-1)], row stride 2K.
// which: 0=Wi0p 1=Wh0p 2=Wi1p 3=Wh1p (gate-row permuted)  4=Xp (no perm)
__global__ void pack_hl_kernel(const float* __restrict__ src, int which, int rows, int K)
{
    bf16* dst = (which == 0) ? g_Wi0p : (which == 1) ? g_Wh0p :
                (which == 2) ? g_Wi1p : (which == 3) ? g_Wh1p : g_Xp;
    bool perm = (which < 4);
    int total = rows * K;
    for (int id = blockIdx.x * blockDim.x + threadIdx.x; id < total;
         id += gridDim.x * blockDim.x) {
        int r = id / K, k = id - r * K;
        int sr = perm ? ((r & 3) * H_ + (r >> 2)) : r;
        float v = src[(size_t)sr * K + k];
        bf16 hi = __float2bfloat16_rn(v);
        bf16 lo = __float2bfloat16_rn(v - __bfloat162float(hi));
        dst[(size_t)r * (2 * K) + k]     = hi;
        dst[(size_t)r * (2 * K) + K + k] = lo;
    }
}

__global__ void bias_kernel(const float* __restrict__ bi0, const float* __restrict__ bh0,
                            const float* __restrict__ bi1, const float* __restrict__ bh1)
{
    int r = blockIdx.x * blockDim.x + threadIdx.x;
    if (r < G_) {
        int sr = (r & 3) * H_ + (r >> 2);
        g_b0[r] = bi0[sr] + bh0[sr];
        g_b1[r] = bi1[sr] + bh1[sr];
    }
}

__global__ void init_state_kernel(const float* __restrict__ h0, const float* __restrict__ c0)
{
    int id = blockIdx.x * blockDim.x + threadIdx.x;
    if (id < 2 * B_ * H_) {
        int l = id / (B_ * H_);
        int b = (id / H_) % B_;
        int j = id % H_;
        float hv = h0[(b * 2 + l) * H_ + j];
        float cv = c0[(b * 2 + l) * H_ + j];
        g_h[id] = hv;
        g_c[id] = cv;
        bf16 hh = __float2bfloat16_rn(hv);
        bf16 hl = __float2bfloat16_rn(hv - __bfloat162float(hh));
        if (l == 0) {
            g_h0p[0][b * 2048 + j]        = hh;
            g_h0p[0][b * 2048 + 1024 + j] = hl;
        } else {
            g_h1p[0][b * 2048 + j]        = hh;
            g_h1p[0][b * 2048 + 1024 + j] = hl;
        }
    }
}

// ---------------- mma helper ----------------
__device__ __forceinline__ void mma16816(float* d,
    uint32_t a0, uint32_t a1, uint32_t a2, uint32_t a3, uint32_t b0, uint32_t b1)
{
    asm volatile(
        "mma.sync.aligned.m16n8k16.row.col.f32.bf16.bf16.f32 "
        "{%0,%1,%2,%3},{%4,%5,%6,%7},{%8,%9},{%0,%1,%2,%3};\n"
        : "+f"(d[0]), "+f"(d[1]), "+f"(d[2]), "+f"(d[3])
        : "r"(a0), "r"(a1), "r"(a2), "r"(a3), "r"(b0), "r"(b1));
}

#define LDU32(s, r, c) (*reinterpret_cast<const uint32_t*>(&(s)[r][c]))

// ---------------- precompute GEMM: G0 = Xp @ Wi0p^T + b0 ----------------
// M=16384, N=4096 (perm), Kreal=512. CTA tile 128x64, 256 threads (8 warps 4x2, warp 32x32).
__global__ __launch_bounds__(256) void precompute_kernel()
{
    __shared__ bf16 sAh[128][40], sAl[128][40], sBh[64][40], sBl[64][40];
    int tid = threadIdx.x;
    int w = tid >> 5, lane = tid & 31, g = lane >> 2, t4 = lane & 3;
    int wm = w & 3, wn = w >> 2;
    int m0 = blockIdx.y * 128, n0 = blockIdx.x * 64;

    float acc[2][4][4];
#pragma unroll
    for (int a = 0; a < 2; a++)
#pragma unroll
        for (int b = 0; b < 4; b++)
#pragma unroll
            for (int c = 0; c < 4; c++) acc[a][b][c] = 0.f;

    for (int k0 = 0; k0 < D_; k0 += 32) {
#pragma unroll
        for (int v = 0; v < 2; v++) {
            int idx = tid + v * 256;
            int r = idx >> 2, kv = (idx & 3) * 8;
            *(uint4*)&sAh[r][kv] = *(const uint4*)&g_Xp[(size_t)(m0 + r) * 1024 + k0 + kv];
            *(uint4*)&sAl[r][kv] = *(const uint4*)&g_Xp[(size_t)(m0 + r) * 1024 + 512 + k0 + kv];
        }
        {
            int r = tid >> 2, kv = (tid & 3) * 8;
            *(uint4*)&sBh[r][kv] = *(const uint4*)&g_Wi0p[(size_t)(n0 + r) * 1024 + k0 + kv];
            *(uint4*)&sBl[r][kv] = *(const uint4*)&g_Wi0p[(size_t)(n0 + r) * 1024 + 512 + k0 + kv];
        }
        __syncthreads();
#pragma unroll
        for (int kk = 0; kk < 2; kk++) {
            int kb = kk * 16;
            uint32_t Ah[2][4], Al[2][4], Bh[4][2], Bl[4][2];
#pragma unroll
            for (int mt = 0; mt < 2; mt++) {
                int ra = wm * 32 + mt * 16;
                Ah[mt][0] = LDU32(sAh, ra + g,     kb + 2 * t4);
                Ah[mt][1] = LDU32(sAh, ra + g + 8, kb + 2 * t4);
                Ah[mt][2] = LDU32(sAh, ra + g,     kb + 2 * t4 + 8);
                Ah[mt][3] = LDU32(sAh, ra + g + 8, kb + 2 * t4 + 8);
                Al[mt][0] = LDU32(sAl, ra + g,     kb + 2 * t4);
                Al[mt][1] = LDU32(sAl, ra + g + 8, kb + 2 * t4);
                Al[mt][2] = LDU32(sAl, ra + g,     kb + 2 * t4 + 8);
                Al[mt][3] = LDU32(sAl, ra + g + 8, kb + 2 * t4 + 8);
            }
#pragma unroll
            for (int nt = 0; nt < 4; nt++) {
                int rb = wn * 32 + nt * 8;
                Bh[nt][0] = LDU32(sBh, rb + g, kb + 2 * t4);
                Bh[nt][1] = LDU32(sBh, rb + g, kb + 2 * t4 + 8);
                Bl[nt][0] = LDU32(sBl, rb + g, kb + 2 * t4);
                Bl[nt][1] = LDU32(sBl, rb + g, kb + 2 * t4 + 8);
            }
#pragma unroll
            for (int mt = 0; mt < 2; mt++)
#pragma unroll
                for (int nt = 0; nt < 4; nt++) {
                    mma16816(acc[mt][nt], Ah[mt][0], Ah[mt][1], Ah[mt][2], Ah[mt][3], Bh[nt][0], Bh[nt][1]);
                    mma16816(acc[mt][nt], Al[mt][0], Al[mt][1], Al[mt][2], Al[mt][3], Bh[nt][0], Bh[nt][1]);
                    mma16816(acc[mt][nt], Ah[mt][0], Ah[mt][1], Ah[mt][2], Ah[mt][3], Bl[nt][0], Bl[nt][1]);
                }
        }
        __syncthreads();
    }
    // epilogue: add bias, store fp32
#pragma unroll
    for (int mt = 0; mt < 2; mt++)
#pragma unroll
        for (int nt = 0; nt < 4; nt++) {
            int row = m0 + wm * 32 + mt * 16 + g;
            int col = n0 + wn * 32 + nt * 8 + 2 * t4;
            float ba = g_b0[col], bb = g_b0[col + 1];
            float2 v0 = make_float2(acc[mt][nt][0] + ba, acc[mt][nt][1] + bb);
            float2 v1 = make_float2(acc[mt][nt][2] + ba, acc[mt][nt][3] + bb);
            *(float2*)&g_G0[(size_t)row * G_ + col]       = v0;
            *(float2*)&g_G0[(size_t)(row + 8) * G_ + col] = v1;
        }
}

__device__ __forceinline__ float sigmoidf_(float z) { return 1.f / (1.f + __expf(-z)); }

// ---------------- per-step GEMM + fused LSTM activation ----------------
// M=64 (batch), CTA N tile = 32 (8 hidden units x 4 gates), grid 128 CTAs, 128 threads.
// LAYER 0: gates = G0[t] + keep * (h0 @ Wh0^T)
// LAYER 1: gates = x @ Wi1^T + keep * (h1 @ Wh1^T) + b1
template <int LAYER>
__global__ __launch_bounds__(128) void step_kernel(int t, const int* __restrict__ reset,
                                                   float* __restrict__ out)
{
    __shared__ bf16 sAh[64][72], sAl[64][72], sBh[32][72], sBl[32][72];
    __shared__ float zs[64][33];

    int tid = threadIdx.x;
    int w = tid >> 5, lane = tid & 31, g = lane >> 2, t4 = lane & 3;
    int wm = w & 1, wn = w >> 1;
    int n0 = blockIdx.x * 32;
    int par = t & 1, parn = (t + 1) & 1;
    int tglob = t * B_;

    const bf16* As[2];
    const bf16* Bs[2];
    if (LAYER == 0) { As[0] = g_h0p[par]; Bs[0] = g_Wh0p; As[1] = nullptr; Bs[1] = nullptr; }
    else            { As[0] = g_x1p[par]; Bs[0] = g_Wi1p; As[1] = g_h1p[par]; Bs[1] = g_Wh1p; }

    float acc[2][2][2][4];
#pragma unroll
    for (int s = 0; s < 2; s++)
#pragma unroll
        for (int a = 0; a < 2; a++)
#pragma unroll
            for (int b = 0; b < 2; b++)
#pragma unroll
                for (int c = 0; c < 4; c++) acc[s][a][b][c] = 0.f;

    const int NSEG = (LAYER == 0) ? 1 : 2;
#pragma unroll
    for (int seg = 0; seg < NSEG; seg++) {
        const bf16* A = As[seg];
        const bf16* B = Bs[seg];
        for (int k0 = 0; k0 < H_; k0 += 64) {
#pragma unroll
            for (int v = 0; v < 4; v++) {
                int idx = tid + v * 128;
                int r = idx >> 3, kv = (idx & 7) * 8;
                *(uint4*)&sAh[r][kv] = *(const uint4*)&A[(size_t)r * 2048 + k0 + kv];
                *(uint4*)&sAl[r][kv] = *(const uint4*)&A[(size_t)r * 2048 + 1024 + k0 + kv];
            }
#pragma unroll
            for (int v = 0; v < 2; v++) {
                int idx = tid + v * 128;
                int r = idx >> 3, kv = (idx & 7) * 8;
                *(uint4*)&sBh[r][kv] = *(const uint4*)&B[(size_t)(n0 + r) * 2048 + k0 + kv];
                *(uint4*)&sBl[r][kv] = *(const uint4*)&B[(size_t)(n0 + r) * 2048 + 1024 + k0 + kv];
            }
            __syncthreads();
#pragma unroll
            for (int kk = 0; kk < 4; kk++) {
                int kb = kk * 16;
                uint32_t Ah[2][4], Al[2][4], Bh[2][2], Bl[2][2];
#pragma unroll
                for (int mt = 0; mt < 2; mt++) {
                    int ra = wm * 32 + mt * 16;
                    Ah[mt][0] = LDU32(sAh, ra + g,     kb + 2 * t4);
                    Ah[mt][1] = LDU32(sAh, ra + g + 8, kb + 2 * t4);
                    Ah[mt][2] = LDU32(sAh, ra + g,     kb + 2 * t4 + 8);
                    Ah[mt][3] = LDU32(sAh, ra + g + 8, kb + 2 * t4 + 8);
                    Al[mt][0] = LDU32(sAl, ra + g,     kb + 2 * t4);
                    Al[mt][1] = LDU32(sAl, ra + g + 8, kb + 2 * t4);
                    Al[mt][2] = LDU32(sAl, ra + g,     kb + 2 * t4 + 8);
                    Al[mt][3] = LDU32(sAl, ra + g + 8, kb + 2 * t4 + 8);
                }
#pragma unroll
                for (int nt = 0; nt < 2; nt++) {
                    int rb = wn * 16 + nt * 8;
                    Bh[nt][0] = LDU32(sBh, rb + g, kb + 2 * t4);
                    Bh[nt][1] = LDU32(sBh, rb + g, kb + 2 * t4 + 8);
                    Bl[nt][0] = LDU32(sBl, rb + g, kb + 2 * t4);
                    Bl[nt][1] = LDU32(sBl, rb + g, kb + 2 * t4 + 8);
                }
#pragma unroll
                for (int mt = 0; mt < 2; mt++)
#pragma unroll
                    for (int nt = 0; nt < 2; nt++) {
                        mma16816(acc[seg][mt][nt], Ah[mt][0], Ah[mt][1], Ah[mt][2], Ah[mt][3], Bh[nt][0], Bh[nt][1]);
                        mma16816(acc[seg][mt][nt], Al[mt][0], Al[mt][1], Al[mt][2], Al[mt][3], Bh[nt][0], Bh[nt][1]);
                        mma16816(acc[seg][mt][nt], Ah[mt][0], Ah[mt][1], Ah[mt][2], Ah[mt][3], Bl[nt][0], Bl[nt][1]);
                    }
            }
            __syncthreads();
        }
    }

    // combine contributions -> preactivations in smem
#pragma unroll
    for (int mt = 0; mt < 2; mt++)
#pragma unroll
        for (int nt = 0; nt < 2; nt++) {
            int rl0 = wm * 32 + mt * 16 + g;
            int cl0 = wn * 16 + nt * 8 + 2 * t4;
#pragma unroll
            for (int half = 0; half < 2; half++) {
                int rl = rl0 + half * 8;
                float keep = 1.0f - (float)reset[tglob + rl];
#pragma unroll
                for (int e = 0; e < 2; e++) {
                    int idx = half * 2 + e;
                    int cl = cl0 + e;
                    float z;
                    if (LAYER == 0)
                        z = g_G0[(size_t)(tglob + rl) * G_ + n0 + cl] + keep * acc[0][mt][nt][idx];
                    else
                        z = acc[0][mt][nt][idx] + keep * acc[1][mt][nt][idx] + g_b1[n0 + cl];
                    zs[rl][cl] = z;
                }
            }
        }
    __syncthreads();

    // fused LSTM activation: 64 batch x 8 hidden units per CTA
#pragma unroll
    for (int q = 0; q < 4; q++) {
        int p = tid + q * 128;
        int b = p >> 3, jl = p & 7;
        float zi = zs[b][4 * jl + 0];
        float zf = zs[b][4 * jl + 1];
        float zg = zs[b][4 * jl + 2];
        float zo = zs[b][4 * jl + 3];
        int j = blockIdx.x * 8 + jl;
        int sidx = (LAYER * B_ + b) * H_ + j;
        float keep = 1.0f - (float)reset[tglob + b];
        float co = g_c[sidx];
        float cn = sigmoidf_(zf) * keep * co + sigmoidf_(zi) * tanhf(zg);
        float hn = sigmoidf_(zo) * tanhf(cn);
        g_c[sidx] = cn;
        g_h[sidx] = hn;
        bf16 hh = __float2bfloat16_rn(hn);
        bf16 hl = __float2bfloat16_rn(hn - __bfloat162float(hh));
        if (LAYER == 0) {
            g_x1p[par][b * 2048 + j]         = hh;
            g_x1p[par][b * 2048 + 1024 + j]  = hl;
            g_h0p[parn][b * 2048 + j]        = hh;
            g_h0p[parn][b * 2048 + 1024 + j] = hl;
        } else {
            out[(size_t)t * B_ * H_ + b * H_ + j] = hn;
            g_h1p[parn][b * 2048 + j]        = hh;
            g_h1p[parn][b * 2048 + 1024 + j] = hl;
        }
    }
}

__global__ void final_kernel(float* __restrict__ out)
{
    int id = blockIdx.x * blockDim.x + threadIdx.x;
    if (id < 2 * B_ * H_) {
        int l = id / (B_ * H_);
        int b = (id / H_) % B_;
        int j = id % H_;
        out[OUTS_ + (b * 2 + l) * H_ + j]               = g_h[id];
        out[OUTS_ + 2 * B_ * H_ + (b * 2 + l) * H_ + j] = g_c[id];
    }
}

// ---------------- launch ----------------
extern "C" void kernel_launch(void* const* d_in, const int* in_sizes, int n_in,
                              void* d_out, int out_size)
{
    (void)in_sizes; (void)n_in; (void)out_size;
    const float* input = (const float*)d_in[0];
    const int*   reset = (const int*)d_in[1];
    const float* h0    = (const float*)d_in[2];
    const float* c0    = (const float*)d_in[3];
    const float* Wi0   = (const float*)d_in[4];
    const float* Wh0   = (const float*)d_in[5];
    const float* bi0   = (const float*)d_in[6];
    const float* bh0   = (const float*)d_in[7];
    const float* Wi1   = (const float*)d_in[8];
    const float* Wh1   = (const float*)d_in[9];
    const float* bi1   = (const float*)d_in[10];
    const float* bh1   = (const float*)d_in[11];
    float* out = (float*)d_out;

    pack_hl_kernel<<<2048, 256>>>(Wi0,   0, G_,  D_);
    pack_hl_kernel<<<2048, 256>>>(Wh0,   1, G_,  H_);
    pack_hl_kernel<<<2048, 256>>>(Wi1,   2, G_,  H_);
    pack_hl_kernel<<<2048, 256>>>(Wh1,   3, G_,  H_);
    pack_hl_kernel<<<2048, 256>>>(input, 4, TB_, D_);
    bias_kernel<<<16, 256>>>(bi0, bh0, bi1, bh1);
    init_state_kernel<<<512, 256>>>(h0, c0);

    precompute_kernel<<<dim3(64, 128), 256>>>();

    for (int t = 0; t < T_; t++) {
        step_kernel<0><<<128, 128>>>(t, reset, out);
        step_kernel<1><<<128, 128>>>(t, reset, out);
    }
    final_kernel<<<512, 256>>>(out);
}

// round 2
// speedup vs baseline: 2.1476x; 2.1476x over previous
#include <cuda_runtime.h>
#include <cuda_bf16.h>
#include <cstdint>
#include <cstddef>

typedef __nv_bfloat16 bf16;

#define T_ 256
#define B_ 64
#define D_ 512
#define H_ 1024
#define G_ 4096
#define TB_ (T_ * B_)
#define OUTS_ (TB_ * H_)
#define NB_ 128          // persistent grid size

// ---------------- device scratch ----------------
__device__ bf16  g_Xp  [(size_t)TB_ * (2 * D_)];
__device__ bf16  g_Wi0p[(size_t)G_  * (2 * D_)];
__device__ bf16  g_Wh0p[(size_t)G_  * (2 * H_)];
__device__ bf16  g_Wi1p[(size_t)G_  * (2 * H_)];
__device__ bf16  g_Wh1p[(size_t)G_  * (2 * H_)];
__device__ float g_b0[G_], g_b1[G_];
__device__ float g_G0[(size_t)TB_ * G_];
__device__ float g_G1[(size_t)TB_ * G_];
__device__ float g_c0s[2 * B_ * H_];
__device__ bf16  g_X1p[(size_t)(T_ + 1) * B_ * 2 * H_];  // slot t = packed h0 out of step t-1
__device__ bf16  g_h1p[2][B_ * 2 * H_];
__device__ unsigned g_bar_arrive;        // zero-init
__device__ volatile unsigned g_bar_gen;  // zero-init

// ---------------- small helpers ----------------
__device__ __forceinline__ void cp_async16(void* sdst, const void* gsrc) {
    uint32_t s = (uint32_t)__cvta_generic_to_shared(sdst);
    asm volatile("cp.async.cg.shared.global [%0], [%1], 16;\n" :: "r"(s), "l"(gsrc));
}
__device__ __forceinline__ void cp_commit() { asm volatile("cp.async.commit_group;\n"); }
template <int N> __device__ __forceinline__ void cp_wait() {
    asm volatile("cp.async.wait_group %0;\n" :: "n"(N));
}

__device__ __forceinline__ void grid_barrier() {
    __threadfence();
    __syncthreads();
    if (threadIdx.x == 0) {
        unsigned gen = g_bar_gen;
        if (atomicAdd(&g_bar_arrive, 1u) == NB_ - 1u) {
            g_bar_arrive = 0;
            __threadfence();
            g_bar_gen = gen + 1;
        } else {
            while (g_bar_gen == gen) { __nanosleep(32); }
        }
    }
    __syncthreads();
}

__device__ __forceinline__ void mma16816(float* d,
    uint32_t a0, uint32_t a1, uint32_t a2, uint32_t a3, uint32_t b0, uint32_t b1)
{
    asm volatile(
        "mma.sync.aligned.m16n8k16.row.col.f32.bf16.bf16.f32 "
        "{%0,%1,%2,%3},{%4,%5,%6,%7},{%8,%9},{%0,%1,%2,%3};\n"
        : "+f"(d[0]), "+f"(d[1]), "+f"(d[2]), "+f"(d[3])
        : "r"(a0), "r"(a1), "r"(a2), "r"(a3), "r"(b0), "r"(b1));
}

__device__ __forceinline__ float sigmoidf_(float z) { return 1.f / (1.f + __expf(-z)); }

// ---------------- packing ----------------
__global__ void pack_hl_kernel(const float* __restrict__ src, int which, int rows, int K)
{
    bf16* dst = (which == 0) ? g_Wi0p : (which == 1) ? g_Wh0p :
                (which == 2) ? g_Wi1p : (which == 3) ? g_Wh1p : g_Xp;
    bool perm = (which < 4);
    int total = rows * K;
    for (int id = blockIdx.x * blockDim.x + threadIdx.x; id < total;
         id += gridDim.x * blockDim.x) {
        int r = id / K, k = id - r * K;
        int sr = perm ? ((r & 3) * H_ + (r >> 2)) : r;
        float v = src[(size_t)sr * K + k];
        bf16 hi = __float2bfloat16_rn(v);
        bf16 lo = __float2bfloat16_rn(v - __bfloat162float(hi));
        dst[(size_t)r * (2 * K) + k]     = hi;
        dst[(size_t)r * (2 * K) + K + k] = lo;
    }
}

__global__ void bias_kernel(const float* __restrict__ bi0, const float* __restrict__ bh0,
                            const float* __restrict__ bi1, const float* __restrict__ bh1)
{
    int r = blockIdx.x * blockDim.x + threadIdx.x;
    if (r < G_) {
        int sr = (r & 3) * H_ + (r >> 2);
        g_b0[r] = bi0[sr] + bh0[sr];
        g_b1[r] = bi1[sr] + bh1[sr];
    }
}

__global__ void init_state_kernel(const float* __restrict__ h0, const float* __restrict__ c0)
{
    int id = blockIdx.x * blockDim.x + threadIdx.x;
    if (id < 2 * B_ * H_) {
        int l = id / (B_ * H_);
        int b = (id / H_) % B_;
        int j = id % H_;
        float hv = h0[(b * 2 + l) * H_ + j];
        g_c0s[id] = c0[(b * 2 + l) * H_ + j];
        bf16 hh = __float2bfloat16_rn(hv);
        bf16 hl = __float2bfloat16_rn(hv - __bfloat162float(hh));
        if (l == 0) {
            g_X1p[b * 2048 + j]        = hh;   // slot 0
            g_X1p[b * 2048 + 1024 + j] = hl;
        } else {
            g_h1p[0][b * 2048 + j]        = hh;
            g_h1p[0][b * 2048 + 1024 + j] = hl;
        }
    }
}

// ---------------- big GEMM (G0 / G1): out = A @ B^T + bias ----------------
// A: M x (2K) packed [hi|lo]; B: 4096 x (2K) packed; out: M x 4096 fp32.
// CTA tile 128x64, 256 threads (8 warps as 2x4), K-chunk 64, cp.async double buffer.
#define GA_STR 136
__global__ __launch_bounds__(256) void gemm_kernel(int sel)
{
    extern __shared__ bf16 sm[];
    const int AS = 128 * GA_STR;   // bf16 elems per A stage
    const int BS = 64 * GA_STR;
    bf16* sA = sm;                 // 2 stages
    bf16* sB = sm + 2 * AS;        // 2 stages

    const bf16 *A, *B; const float* bias; float* outp; int K;
    if (sel == 0) { A = g_Xp;  B = g_Wi0p; bias = g_b0; outp = g_G0; K = 512; }
    else { A = g_X1p + (size_t)B_ * 2048; B = g_Wi1p; bias = g_b1; outp = g_G1; K = 1024; }

    int tid = threadIdx.x, w = tid >> 5, lane = tid & 31, g = lane >> 2, t4 = lane & 3;
    int wm = w & 1, wn = w >> 1;
    int m0 = blockIdx.y * 128, n0 = blockIdx.x * 64;
    int rs = 2 * K;
    int NC = K / 64;

    float acc[4][2][4];
#pragma unroll
    for (int a = 0; a < 4; a++)
#pragma unroll
        for (int b = 0; b < 2; b++)
#pragma unroll
            for (int c = 0; c < 4; c++) acc[a][b][c] = 0.f;

    auto issue = [&](int c) {
        int k0 = c * 64;
        int st = c & 1;
#pragma unroll
        for (int v = 0; v < 8; v++) {           // A: 128 rows x 16 segs
            int idx = tid + v * 256;
            int r = idx >> 4, s = idx & 15;
            int src = (s < 8) ? (k0 + s * 8) : (K + k0 + (s - 8) * 8);
            cp_async16(&sA[st * AS + r * GA_STR + s * 8], &A[(size_t)(m0 + r) * rs + src]);
        }
#pragma unroll
        for (int v = 0; v < 4; v++) {           // B: 64 rows x 16 segs
            int idx = tid + v * 256;
            int r = idx >> 4, s = idx & 15;
            int src = (s < 8) ? (k0 + s * 8) : (K + k0 + (s - 8) * 8);
            cp_async16(&sB[st * BS + r * GA_STR + s * 8], &B[(size_t)(n0 + r) * rs + src]);
        }
        cp_commit();
    };

    issue(0);
    for (int c = 0; c < NC; c++) {
        if (c + 1 < NC) { issue(c + 1); cp_wait<1>(); }
        else cp_wait<0>();
        __syncthreads();
        const bf16* Ab = sA + (c & 1) * AS;
        const bf16* Bb = sB + (c & 1) * BS;
#pragma unroll
        for (int kk = 0; kk < 4; kk++) {
            int kb = kk * 16;
            uint32_t Ah[4][4], Al[4][4], Bh[2][2], Bl[2][2];
#pragma unroll
            for (int mt = 0; mt < 4; mt++) {
                int ra = wm * 64 + mt * 16;
                Ah[mt][0] = *(const uint32_t*)&Ab[(ra + g) * GA_STR + kb + 2 * t4];
                Ah[mt][1] = *(const uint32_t*)&Ab[(ra + g + 8) * GA_STR + kb + 2 * t4];
                Ah[mt][2] = *(const uint32_t*)&Ab[(ra + g) * GA_STR + kb + 2 * t4 + 8];
                Ah[mt][3] = *(const uint32_t*)&Ab[(ra + g + 8) * GA_STR + kb + 2 * t4 + 8];
                Al[mt][0] = *(const uint32_t*)&Ab[(ra + g) * GA_STR + 64 + kb + 2 * t4];
                Al[mt][1] = *(const uint32_t*)&Ab[(ra + g + 8) * GA_STR + 64 + kb + 2 * t4];
                Al[mt][2] = *(const uint32_t*)&Ab[(ra + g) * GA_STR + 64 + kb + 2 * t4 + 8];
                Al[mt][3] = *(const uint32_t*)&Ab[(ra + g + 8) * GA_STR + 64 + kb + 2 * t4 + 8];
            }
#pragma unroll
            for (int nt = 0; nt < 2; nt++) {
                int rb = wn * 16 + nt * 8;
                Bh[nt][0] = *(const uint32_t*)&Bb[(rb + g) * GA_STR + kb + 2 * t4];
                Bh[nt][1] = *(const uint32_t*)&Bb[(rb + g) * GA_STR + kb + 2 * t4 + 8];
                Bl[nt][0] = *(const uint32_t*)&Bb[(rb + g) * GA_STR + 64 + kb + 2 * t4];
                Bl[nt][1] = *(const uint32_t*)&Bb[(rb + g) * GA_STR + 64 + kb + 2 * t4 + 8];
            }
#pragma unroll
            for (int mt = 0; mt < 4; mt++)
#pragma unroll
                for (int nt = 0; nt < 2; nt++) {
                    mma16816(acc[mt][nt], Ah[mt][0], Ah[mt][1], Ah[mt][2], Ah[mt][3], Bh[nt][0], Bh[nt][1]);
                    mma16816(acc[mt][nt], Al[mt][0], Al[mt][1], Al[mt][2], Al[mt][3], Bh[nt][0], Bh[nt][1]);
                    mma16816(acc[mt][nt], Ah[mt][0], Ah[mt][1], Ah[mt][2], Ah[mt][3], Bl[nt][0], Bl[nt][1]);
                }
        }
        __syncthreads();
    }

#pragma unroll
    for (int mt = 0; mt < 4; mt++)
#pragma unroll
        for (int nt = 0; nt < 2; nt++) {
            int row = m0 + wm * 64 + mt * 16 + g;
            int col = n0 + wn * 16 + nt * 8 + 2 * t4;
            float ba = bias[col], bb = bias[col + 1];
            *(float2*)&outp[(size_t)row * G_ + col] =
                make_float2(acc[mt][nt][0] + ba, acc[mt][nt][1] + bb);
            *(float2*)&outp[(size_t)(row + 8) * G_ + col] =
                make_float2(acc[mt][nt][2] + ba, acc[mt][nt][3] + bb);
        }
}

// ---------------- persistent layer kernel ----------------
// 128 CTAs x 256 threads. CTA owns 32 gate-cols (8 hidden units). Wh slice in SMEM.
// 256 steps; per step: gates = Gpre[t] + keep*(h_prev @ Wh^T); fused activation.
#define WSTR 2056
#define ASTR 136
__global__ __launch_bounds__(256, 1) void layer_kernel0(const int* __restrict__ reset, float* __restrict__ out);
__global__ __launch_bounds__(256, 1) void layer_kernel1(const int* __restrict__ reset, float* __restrict__ out);

template <int LAYER>
__device__ __forceinline__ void layer_body(const int* __restrict__ reset, float* __restrict__ out)
{
    extern __shared__ bf16 smem[];
    bf16* sW = smem;                       // 32 x WSTR
    bf16* sA = smem + 32 * WSTR;           // 2 x 64 x ASTR
    float* zs = (float*)(sA + 2 * 64 * ASTR);  // 64 x 36

    int tid = threadIdx.x, w = tid >> 5, lane = tid & 31, g = lane >> 2, t4 = lane & 3;
    int wm = w & 1, wn = w >> 1;
    int n0 = blockIdx.x * 32;

    // load weight slice once
    const bf16* Wsrc = (LAYER == 0 ? g_Wh0p : g_Wh1p) + (size_t)n0 * 2048;
    for (int i = tid; i < 32 * 256; i += 256) {
        int r = i >> 8, s = i & 255;
        *(uint4*)&sW[r * WSTR + s * 8] = *(const uint4*)&Wsrc[(size_t)r * 2048 + s * 8];
    }

    const float* Gpre = (LAYER == 0) ? g_G0 : g_G1;

    // c state in registers
    float c_reg[2];
#pragma unroll
    for (int it = 0; it < 2; it++) {
        int idx = tid + it * 256;
        int b = idx >> 3, jl = idx & 7, j = blockIdx.x * 8 + jl;
        c_reg[it] = g_c0s[(LAYER * B_ + b) * H_ + j];
    }
    __syncthreads();

    for (int t = 0; t < T_; t++) {
        const bf16* Asrc = (LAYER == 0) ? (g_X1p + (size_t)t * B_ * 2048) : g_h1p[t & 1];
        bf16* Adst = (LAYER == 0) ? (g_X1p + (size_t)(t + 1) * B_ * 2048) : g_h1p[(t + 1) & 1];

        float acc[2][4];
#pragma unroll
        for (int a = 0; a < 2; a++)
#pragma unroll
            for (int c = 0; c < 4; c++) acc[a][c] = 0.f;

        auto issue = [&](int c) {
            int k0 = c * 64, st = c & 1;
#pragma unroll
            for (int v = 0; v < 4; v++) {       // 64 rows x 16 segs
                int idx = tid + v * 256;
                int r = idx >> 4, s = idx & 15;
                int src = (s < 8) ? (k0 + s * 8) : (1024 + k0 + (s - 8) * 8);
                cp_async16(&sA[st * 64 * ASTR + r * ASTR + s * 8], &Asrc[(size_t)r * 2048 + src]);
            }
            cp_commit();
        };

        issue(0);
        for (int c = 0; c < 16; c++) {
            if (c + 1 < 16) { issue(c + 1); cp_wait<1>(); }
            else cp_wait<0>();
            __syncthreads();
            const bf16* Ab = sA + (c & 1) * 64 * ASTR;
            int k0 = c * 64;
#pragma unroll
            for (int kk = 0; kk < 4; kk++) {
                int kb = kk * 16;
                uint32_t Ah[2][4], Al[2][4], Bh[2], Bl[2];
#pragma unroll
                for (int mt = 0; mt < 2; mt++) {
                    int ra = wm * 32 + mt * 16;
                    Ah[mt][0] = *(const uint32_t*)&Ab[(ra + g) * ASTR + kb + 2 * t4];
                    Ah[mt][1] = *(const uint32_t*)&Ab[(ra + g + 8) * ASTR + kb + 2 * t4];
                    Ah[mt][2] = *(const uint32_t*)&Ab[(ra + g) * ASTR + kb + 2 * t4 + 8];
                    Ah[mt][3] = *(const uint32_t*)&Ab[(ra + g + 8) * ASTR + kb + 2 * t4 + 8];
                    Al[mt][0] = *(const uint32_t*)&Ab[(ra + g) * ASTR + 64 + kb + 2 * t4];
                    Al[mt][1] = *(const uint32_t*)&Ab[(ra + g + 8) * ASTR + 64 + kb + 2 * t4];
                    Al[mt][2] = *(const uint32_t*)&Ab[(ra + g) * ASTR + 64 + kb + 2 * t4 + 8];
                    Al[mt][3] = *(const uint32_t*)&Ab[(ra + g + 8) * ASTR + 64 + kb + 2 * t4 + 8];
                }
                {
                    int rb = wn * 8 + g;
                    Bh[0] = *(const uint32_t*)&sW[rb * WSTR + k0 + kb + 2 * t4];
                    Bh[1] = *(const uint32_t*)&sW[rb * WSTR + k0 + kb + 2 * t4 + 8];
                    Bl[0] = *(const uint32_t*)&sW[rb * WSTR + 1024 + k0 + kb + 2 * t4];
                    Bl[1] = *(const uint32_t*)&sW[rb * WSTR + 1024 + k0 + kb + 2 * t4 + 8];
                }
#pragma unroll
                for (int mt = 0; mt < 2; mt++) {
                    mma16816(acc[mt], Ah[mt][0], Ah[mt][1], Ah[mt][2], Ah[mt][3], Bh[0], Bh[1]);
                    mma16816(acc[mt], Al[mt][0], Al[mt][1], Al[mt][2], Al[mt][3], Bh[0], Bh[1]);
                    mma16816(acc[mt], Ah[mt][0], Ah[mt][1], Ah[mt][2], Ah[mt][3], Bl[0], Bl[1]);
                }
            }
            __syncthreads();
        }

        // write hsum to smem
#pragma unroll
        for (int mt = 0; mt < 2; mt++) {
            int r0 = wm * 32 + mt * 16 + g;
            int c0 = wn * 8 + 2 * t4;
            zs[r0 * 36 + c0]     = acc[mt][0];
            zs[r0 * 36 + c0 + 1] = acc[mt][1];
            zs[(r0 + 8) * 36 + c0]     = acc[mt][2];
            zs[(r0 + 8) * 36 + c0 + 1] = acc[mt][3];
        }
        __syncthreads();

        // fused activation
#pragma unroll
        for (int it = 0; it < 2; it++) {
            int idx = tid + it * 256;
            int b = idx >> 3, jl = idx & 7, j = blockIdx.x * 8 + jl;
            float keep = 1.0f - (float)reset[t * B_ + b];
            float4 gp = *(const float4*)&Gpre[((size_t)t * B_ + b) * G_ + n0 + 4 * jl];
            float zi = gp.x + keep * zs[b * 36 + 4 * jl + 0];
            float zf = gp.y + keep * zs[b * 36 + 4 * jl + 1];
            float zg = gp.z + keep * zs[b * 36 + 4 * jl + 2];
            float zo = gp.w + keep * zs[b * 36 + 4 * jl + 3];
            float cn = sigmoidf_(zf) * keep * c_reg[it] + sigmoidf_(zi) * tanhf(zg);
            float hn = sigmoidf_(zo) * tanhf(cn);
            c_reg[it] = cn;
            bf16 hh = __float2bfloat16_rn(hn);
            bf16 hl = __float2bfloat16_rn(hn - __bfloat162float(hh));
            Adst[b * 2048 + j]        = hh;
            Adst[b * 2048 + 1024 + j] = hl;
            if (LAYER == 1)
                out[(size_t)t * B_ * H_ + b * H_ + j] = hn;
            if (t == T_ - 1) {
                out[OUTS_ + (b * 2 + LAYER) * H_ + j] = hn;
                out[OUTS_ + 2 * B_ * H_ + (b * 2 + LAYER) * H_ + j] = cn;
            }
        }
        grid_barrier();
    }
}

__global__ __launch_bounds__(256, 1) void layer_kernel0(const int* __restrict__ reset, float* __restrict__ out)
{ layer_body<0>(reset, out); }
__global__ __launch_bounds__(256, 1) void layer_kernel1(const int* __restrict__ reset, float* __restrict__ out)
{ layer_body<1>(reset, out); }

// ---------------- launch ----------------
extern "C" void kernel_launch(void* const* d_in, const int* in_sizes, int n_in,
                              void* d_out, int out_size)
{
    (void)in_sizes; (void)n_in; (void)out_size;
    const float* input = (const float*)d_in[0];
    const int*   reset = (const int*)d_in[1];
    const float* h0    = (const float*)d_in[2];
    const float* c0    = (const float*)d_in[3];
    const float* Wi0   = (const float*)d_in[4];
    const float* Wh0   = (const float*)d_in[5];
    const float* bi0   = (const float*)d_in[6];
    const float* bh0   = (const float*)d_in[7];
    const float* Wi1   = (const float*)d_in[8];
    const float* Wh1   = (const float*)d_in[9];
    const float* bi1   = (const float*)d_in[10];
    const float* bh1   = (const float*)d_in[11];
    float* out = (float*)d_out;

    const int GEMM_SMEM  = 2 * (128 * GA_STR + 64 * GA_STR) * 2;          // 104448 B
    const int LAYER_SMEM = (32 * WSTR + 2 * 64 * ASTR) * 2 + 64 * 36 * 4; // 175616 B
    cudaFuncSetAttribute(gemm_kernel,  cudaFuncAttributeMaxDynamicSharedMemorySize, GEMM_SMEM);
    cudaFuncSetAttribute(layer_kernel0, cudaFuncAttributeMaxDynamicSharedMemorySize, LAYER_SMEM);
    cudaFuncSetAttribute(layer_kernel1, cudaFuncAttributeMaxDynamicSharedMemorySize, LAYER_SMEM);

    pack_hl_kernel<<<2048, 256>>>(Wi0,   0, G_,  D_);
    pack_hl_kernel<<<2048, 256>>>(Wh0,   1, G_,  H_);
    pack_hl_kernel<<<2048, 256>>>(Wi1,   2, G_,  H_);
    pack_hl_kernel<<<2048, 256>>>(Wh1,   3, G_,  H_);
    pack_hl_kernel<<<2048, 256>>>(input, 4, TB_, D_);
    bias_kernel<<<16, 256>>>(bi0, bh0, bi1, bh1);
    init_state_kernel<<<512, 256>>>(h0, c0);

    gemm_kernel<<<dim3(64, 128), 256, GEMM_SMEM>>>(0);   // G0
    layer_kernel0<<<NB_, 256, LAYER_SMEM>>>(reset, out); // layer 0, 256 steps
    gemm_kernel<<<dim3(64, 128), 256, GEMM_SMEM>>>(1);   // G1
    layer_kernel1<<<NB_, 256, LAYER_SMEM>>>(reset, out); // layer 1, 256 steps
}

// round 3
// speedup vs baseline: 2.2615x; 1.0530x over previous
#include <cuda_runtime.h>
#include <cuda_bf16.h>
#include <cstdint>
#include <cstddef>

typedef __nv_bfloat16 bf16;

#define T_ 256
#define B_ 64
#define D_ 512
#define H_ 1024
#define G_ 4096
#define TB_ (T_ * B_)
#define OUTS_ (TB_ * H_)
#define NB_ 128          // persistent grid size

// ---------------- device scratch ----------------
__device__ bf16  g_Xp  [(size_t)TB_ * (2 * D_)];
__device__ bf16  g_Wi0p[(size_t)G_  * (2 * D_)];
__device__ bf16  g_Wh0p[(size_t)G_  * (2 * H_)];
__device__ bf16  g_Wi1p[(size_t)G_  * (2 * H_)];
__device__ bf16  g_Wh1p[(size_t)G_  * (2 * H_)];
__device__ float g_b0[G_], g_b1[G_];
__device__ float g_G0[(size_t)TB_ * G_];
__device__ float g_G1[(size_t)TB_ * G_];
__device__ float g_c0s[2 * B_ * H_];
__device__ bf16  g_X1p[(size_t)(T_ + 1) * B_ * 2 * H_];
__device__ bf16  g_h1p[2][B_ * 2 * H_];
__device__ unsigned g_bar_arrive;   // zero-init
__device__ unsigned g_bar_gen;      // zero-init (monotonic across launches/replays)

// ---------------- small helpers ----------------
__device__ __forceinline__ void cp_async16(void* sdst, const void* gsrc) {
    uint32_t s = (uint32_t)__cvta_generic_to_shared(sdst);
    asm volatile("cp.async.cg.shared.global [%0], [%1], 16;\n" :: "r"(s), "l"(gsrc));
}
__device__ __forceinline__ void cp_commit() { asm volatile("cp.async.commit_group;\n"); }
template <int N> __device__ __forceinline__ void cp_wait() {
    asm volatile("cp.async.wait_group %0;\n" :: "n"(N));
}
__device__ __forceinline__ unsigned ld_acq(const unsigned* p) {
    unsigned v; asm volatile("ld.acquire.gpu.u32 %0, [%1];" : "=r"(v) : "l"(p)); return v;
}

__device__ __forceinline__ void mma16816(float* d,
    uint32_t a0, uint32_t a1, uint32_t a2, uint32_t a3, uint32_t b0, uint32_t b1)
{
    asm volatile(
        "mma.sync.aligned.m16n8k16.row.col.f32.bf16.bf16.f32 "
        "{%0,%1,%2,%3},{%4,%5,%6,%7},{%8,%9},{%0,%1,%2,%3};\n"
        : "+f"(d[0]), "+f"(d[1]), "+f"(d[2]), "+f"(d[3])
        : "r"(a0), "r"(a1), "r"(a2), "r"(a3), "r"(b0), "r"(b1));
}

__device__ __forceinline__ float sigmoidf_(float z) { return 1.f / (1.f + __expf(-z)); }

// ---------------- packing (float4 vectorized) ----------------
__global__ void pack_hl_kernel(const float* __restrict__ src, int which, int rows, int K)
{
    bf16* dst = (which == 0) ? g_Wi0p : (which == 1) ? g_Wh0p :
                (which == 2) ? g_Wi1p : (which == 3) ? g_Wh1p : g_Xp;
    bool perm = (which < 4);
    int K4 = K >> 2;
    int total = rows * K4;
    for (int id = blockIdx.x * blockDim.x + threadIdx.x; id < total;
         id += gridDim.x * blockDim.x) {
        int r = id / K4, k4 = (id - r * K4) * 4;
        int sr = perm ? ((r & 3) * H_ + (r >> 2)) : r;
        float4 v = *(const float4*)&src[(size_t)sr * K + k4];
        bf16 h0 = __float2bfloat16_rn(v.x), h1 = __float2bfloat16_rn(v.y);
        bf16 h2 = __float2bfloat16_rn(v.z), h3 = __float2bfloat16_rn(v.w);
        bf16 l0 = __float2bfloat16_rn(v.x - __bfloat162float(h0));
        bf16 l1 = __float2bfloat16_rn(v.y - __bfloat162float(h1));
        bf16 l2 = __float2bfloat16_rn(v.z - __bfloat162float(h2));
        bf16 l3 = __float2bfloat16_rn(v.w - __bfloat162float(h3));
        __nv_bfloat162 hv0 = {h0, h1}, hv1 = {h2, h3}, lv0 = {l0, l1}, lv1 = {l2, l3};
        *(uint2*)&dst[(size_t)r * (2 * K) + k4]     = make_uint2(*(uint32_t*)&hv0, *(uint32_t*)&hv1);
        *(uint2*)&dst[(size_t)r * (2 * K) + K + k4] = make_uint2(*(uint32_t*)&lv0, *(uint32_t*)&lv1);
    }
}

__global__ void bias_kernel(const float* __restrict__ bi0, const float* __restrict__ bh0,
                            const float* __restrict__ bi1, const float* __restrict__ bh1)
{
    int r = blockIdx.x * blockDim.x + threadIdx.x;
    if (r < G_) {
        int sr = (r & 3) * H_ + (r >> 2);
        g_b0[r] = bi0[sr] + bh0[sr];
        g_b1[r] = bi1[sr] + bh1[sr];
    }
}

__global__ void init_state_kernel(const float* __restrict__ h0, const float* __restrict__ c0)
{
    int id = blockIdx.x * blockDim.x + threadIdx.x;
    if (id < 2 * B_ * H_) {
        int l = id / (B_ * H_);
        int b = (id / H_) % B_;
        int j = id % H_;
        float hv = h0[(b * 2 + l) * H_ + j];
        g_c0s[id] = c0[(b * 2 + l) * H_ + j];
        bf16 hh = __float2bfloat16_rn(hv);
        bf16 hl = __float2bfloat16_rn(hv - __bfloat162float(hh));
        if (l == 0) {
            g_X1p[b * 2048 + j]        = hh;
            g_X1p[b * 2048 + 1024 + j] = hl;
        } else {
            g_h1p[0][b * 2048 + j]        = hh;
            g_h1p[0][b * 2048 + 1024 + j] = hl;
        }
    }
}

// ---------------- big GEMM: out = A @ B^T + bias ----------------
// CTA tile 128x128, 256 threads (8 warps 2(M) x 4(N), warp tile 64x32),
// K-chunk 64, 3-stage cp.async ring, one __syncthreads per chunk.
#define GA_STR 136
__global__ __launch_bounds__(256) void gemm_kernel(int sel)
{
    extern __shared__ bf16 sm[];
    const int AS = 128 * GA_STR;
    bf16* sA = sm;             // 3 stages
    bf16* sB = sm + 3 * AS;    // 3 stages

    const bf16 *A, *B; const float* bias; float* outp; int K;
    if (sel == 0) { A = g_Xp;  B = g_Wi0p; bias = g_b0; outp = g_G0; K = 512; }
    else { A = g_X1p + (size_t)B_ * 2048; B = g_Wi1p; bias = g_b1; outp = g_G1; K = 1024; }

    int tid = threadIdx.x, w = tid >> 5, lane = tid & 31, g = lane >> 2, t4 = lane & 3;
    int wm = w & 1, wn = w >> 1;
    int m0 = blockIdx.y * 128, n0 = blockIdx.x * 128;
    int rs = 2 * K;
    int NC = K / 64;

    float acc[4][4][4];
#pragma unroll
    for (int a = 0; a < 4; a++)
#pragma unroll
        for (int b = 0; b < 4; b++)
#pragma unroll
            for (int c = 0; c < 4; c++) acc[a][b][c] = 0.f;

    auto issue = [&](int c) {
        int k0 = c * 64;
        int st = c % 3;
#pragma unroll
        for (int v = 0; v < 8; v++) {
            int idx = tid + v * 256;
            int r = idx >> 4, s = idx & 15;
            int src = (s < 8) ? (k0 + s * 8) : (K + k0 + (s - 8) * 8);
            cp_async16(&sA[st * AS + r * GA_STR + s * 8], &A[(size_t)(m0 + r) * rs + src]);
        }
#pragma unroll
        for (int v = 0; v < 8; v++) {
            int idx = tid + v * 256;
            int r = idx >> 4, s = idx & 15;
            int src = (s < 8) ? (k0 + s * 8) : (K + k0 + (s - 8) * 8);
            cp_async16(&sB[st * AS + r * GA_STR + s * 8], &B[(size_t)(n0 + r) * rs + src]);
        }
        cp_commit();
    };

    issue(0); issue(1);
    for (int c = 0; c < NC; c++) {
        if (c + 1 < NC) cp_wait<1>(); else cp_wait<0>();
        __syncthreads();
        if (c + 2 < NC) issue(c + 2);
        const bf16* Ab = sA + (c % 3) * AS;
        const bf16* Bb = sB + (c % 3) * AS;
#pragma unroll
        for (int kk = 0; kk < 4; kk++) {
            int kb = kk * 16;
            uint32_t Ah[4][4], Al[4][4], Bh[4][2], Bl[4][2];
#pragma unroll
            for (int mt = 0; mt < 4; mt++) {
                int ra = wm * 64 + mt * 16;
                Ah[mt][0] = *(const uint32_t*)&Ab[(ra + g) * GA_STR + kb + 2 * t4];
                Ah[mt][1] = *(const uint32_t*)&Ab[(ra + g + 8) * GA_STR + kb + 2 * t4];
                Ah[mt][2] = *(const uint32_t*)&Ab[(ra + g) * GA_STR + kb + 2 * t4 + 8];
                Ah[mt][3] = *(const uint32_t*)&Ab[(ra + g + 8) * GA_STR + kb + 2 * t4 + 8];
                Al[mt][0] = *(const uint32_t*)&Ab[(ra + g) * GA_STR + 64 + kb + 2 * t4];
                Al[mt][1] = *(const uint32_t*)&Ab[(ra + g + 8) * GA_STR + 64 + kb + 2 * t4];
                Al[mt][2] = *(const uint32_t*)&Ab[(ra + g) * GA_STR + 64 + kb + 2 * t4 + 8];
                Al[mt][3] = *(const uint32_t*)&Ab[(ra + g + 8) * GA_STR + 64 + kb + 2 * t4 + 8];
            }
#pragma unroll
            for (int nt = 0; nt < 4; nt++) {
                int rb = wn * 32 + nt * 8;
                Bh[nt][0] = *(const uint32_t*)&Bb[(rb + g) * GA_STR + kb + 2 * t4];
                Bh[nt][1] = *(const uint32_t*)&Bb[(rb + g) * GA_STR + kb + 2 * t4 + 8];
                Bl[nt][0] = *(const uint32_t*)&Bb[(rb + g) * GA_STR + 64 + kb + 2 * t4];
                Bl[nt][1] = *(const uint32_t*)&Bb[(rb + g) * GA_STR + 64 + kb + 2 * t4 + 8];
            }
#pragma unroll
            for (int mt = 0; mt < 4; mt++)
#pragma unroll
                for (int nt = 0; nt < 4; nt++) {
                    mma16816(acc[mt][nt], Ah[mt][0], Ah[mt][1], Ah[mt][2], Ah[mt][3], Bh[nt][0], Bh[nt][1]);
                    mma16816(acc[mt][nt], Al[mt][0], Al[mt][1], Al[mt][2], Al[mt][3], Bh[nt][0], Bh[nt][1]);
                    mma16816(acc[mt][nt], Ah[mt][0], Ah[mt][1], Ah[mt][2], Ah[mt][3], Bl[nt][0], Bl[nt][1]);
                }
        }
    }

#pragma unroll
    for (int mt = 0; mt < 4; mt++)
#pragma unroll
        for (int nt = 0; nt < 4; nt++) {
            int row = m0 + wm * 64 + mt * 16 + g;
            int col = n0 + wn * 32 + nt * 8 + 2 * t4;
            float ba = bias[col], bb = bias[col + 1];
            *(float2*)&outp[(size_t)row * G_ + col] =
                make_float2(acc[mt][nt][0] + ba, acc[mt][nt][1] + bb);
            *(float2*)&outp[(size_t)(row + 8) * G_ + col] =
                make_float2(acc[mt][nt][2] + ba, acc[mt][nt][3] + bb);
        }
}

// ---------------- persistent layer kernel ----------------
#define WSTR 2056
#define ASTR 136

template <int LAYER>
__device__ __forceinline__ void layer_body(const int* __restrict__ reset, float* __restrict__ out)
{
    extern __shared__ bf16 smem[];
    bf16* sW = smem;                           // 32 x WSTR
    bf16* sA = smem + 32 * WSTR;               // 3 x 64 x ASTR
    float* zs = (float*)(sA + 3 * 64 * ASTR);  // 64 x 36

    int tid = threadIdx.x, w = tid >> 5, lane = tid & 31, g = lane >> 2, t4 = lane & 3;
    int wm = w & 1, wn = w >> 1;
    int n0 = blockIdx.x * 32;
    unsigned gen0 = ld_acq(&g_bar_gen);

    const bf16* Wsrc = (LAYER == 0 ? g_Wh0p : g_Wh1p) + (size_t)n0 * 2048;
    for (int i = tid; i < 32 * 256; i += 256) {
        int r = i >> 8, s = i & 255;
        *(uint4*)&sW[r * WSTR + s * 8] = *(const uint4*)&Wsrc[(size_t)r * 2048 + s * 8];
    }

    const float* Gpre = (LAYER == 0) ? g_G0 : g_G1;

    // per-thread activation slot: b, jl
    int bb = tid >> 3, jl = tid & 7, j = blockIdx.x * 8 + jl;
    int bb2 = (tid + 256) >> 3;

    float c_reg[2];
    c_reg[0] = g_c0s[(LAYER * B_ + bb) * H_ + j];
    c_reg[1] = g_c0s[(LAYER * B_ + bb2) * H_ + j];

    // prefetch step-0 Gpre + reset
    float4 gp[2]; int rst[2];
    gp[0] = *(const float4*)&Gpre[(size_t)bb * G_ + n0 + 4 * jl];
    gp[1] = *(const float4*)&Gpre[(size_t)bb2 * G_ + n0 + 4 * jl];
    rst[0] = reset[bb];
    rst[1] = reset[bb2];
    __syncthreads();

    for (int t = 0; t < T_; t++) {
        const bf16* Asrc = (LAYER == 0) ? (g_X1p + (size_t)t * B_ * 2048) : g_h1p[t & 1];
        bf16* Adst = (LAYER == 0) ? (g_X1p + (size_t)(t + 1) * B_ * 2048) : g_h1p[(t + 1) & 1];

        float acc[2][4];
#pragma unroll
        for (int a = 0; a < 2; a++)
#pragma unroll
            for (int c = 0; c < 4; c++) acc[a][c] = 0.f;

        auto issue = [&](int c) {
            int k0 = c * 64, st = c % 3;
#pragma unroll
            for (int v = 0; v < 4; v++) {
                int idx = tid + v * 256;
                int r = idx >> 4, s = idx & 15;
                int src = (s < 8) ? (k0 + s * 8) : (1024 + k0 + (s - 8) * 8);
                cp_async16(&sA[st * 64 * ASTR + r * ASTR + s * 8], &Asrc[(size_t)r * 2048 + src]);
            }
            cp_commit();
        };

        issue(0); issue(1);
        for (int c = 0; c < 16; c++) {
            if (c + 1 < 16) cp_wait<1>(); else cp_wait<0>();
            __syncthreads();
            if (c + 2 < 16) issue(c + 2);
            const bf16* Ab = sA + (c % 3) * 64 * ASTR;
            int k0 = c * 64;
#pragma unroll
            for (int kk = 0; kk < 4; kk++) {
                int kb = kk * 16;
                uint32_t Ah[2][4], Al[2][4], Bh[2], Bl[2];
#pragma unroll
                for (int mt = 0; mt < 2; mt++) {
                    int ra = wm * 32 + mt * 16;
                    Ah[mt][0] = *(const uint32_t*)&Ab[(ra + g) * ASTR + kb + 2 * t4];
                    Ah[mt][1] = *(const uint32_t*)&Ab[(ra + g + 8) * ASTR + kb + 2 * t4];
                    Ah[mt][2] = *(const uint32_t*)&Ab[(ra + g) * ASTR + kb + 2 * t4 + 8];
                    Ah[mt][3] = *(const uint32_t*)&Ab[(ra + g + 8) * ASTR + kb + 2 * t4 + 8];
                    Al[mt][0] = *(const uint32_t*)&Ab[(ra + g) * ASTR + 64 + kb + 2 * t4];
                    Al[mt][1] = *(const uint32_t*)&Ab[(ra + g + 8) * ASTR + 64 + kb + 2 * t4];
                    Al[mt][2] = *(const uint32_t*)&Ab[(ra + g) * ASTR + 64 + kb + 2 * t4 + 8];
                    Al[mt][3] = *(const uint32_t*)&Ab[(ra + g + 8) * ASTR + 64 + kb + 2 * t4 + 8];
                }
                {
                    int rb = wn * 8 + g;
                    Bh[0] = *(const uint32_t*)&sW[rb * WSTR + k0 + kb + 2 * t4];
                    Bh[1] = *(const uint32_t*)&sW[rb * WSTR + k0 + kb + 2 * t4 + 8];
                    Bl[0] = *(const uint32_t*)&sW[rb * WSTR + 1024 + k0 + kb + 2 * t4];
                    Bl[1] = *(const uint32_t*)&sW[rb * WSTR + 1024 + k0 + kb + 2 * t4 + 8];
                }
#pragma unroll
                for (int mt = 0; mt < 2; mt++) {
                    mma16816(acc[mt], Ah[mt][0], Ah[mt][1], Ah[mt][2], Ah[mt][3], Bh[0], Bh[1]);
                    mma16816(acc[mt], Al[mt][0], Al[mt][1], Al[mt][2], Al[mt][3], Bh[0], Bh[1]);
                    mma16816(acc[mt], Ah[mt][0], Ah[mt][1], Ah[mt][2], Ah[mt][3], Bl[0], Bl[1]);
                }
            }
        }

        // preactivation sums -> smem
        __syncthreads();
#pragma unroll
        for (int mt = 0; mt < 2; mt++) {
            int r0 = wm * 32 + mt * 16 + g;
            int c0 = wn * 8 + 2 * t4;
            zs[r0 * 36 + c0]     = acc[mt][0];
            zs[r0 * 36 + c0 + 1] = acc[mt][1];
            zs[(r0 + 8) * 36 + c0]     = acc[mt][2];
            zs[(r0 + 8) * 36 + c0 + 1] = acc[mt][3];
        }
        __syncthreads();

        // fused activation (prefetched gp/rst), store packed h
        float hn_s[2], cn_s[2];
#pragma unroll
        for (int it = 0; it < 2; it++) {
            int b = it ? bb2 : bb;
            float keep = 1.0f - (float)rst[it];
            float zi = gp[it].x + keep * zs[b * 36 + 4 * jl + 0];
            float zf = gp[it].y + keep * zs[b * 36 + 4 * jl + 1];
            float zg = gp[it].z + keep * zs[b * 36 + 4 * jl + 2];
            float zo = gp[it].w + keep * zs[b * 36 + 4 * jl + 3];
            float cn = sigmoidf_(zf) * keep * c_reg[it] + sigmoidf_(zi) * tanhf(zg);
            float hn = sigmoidf_(zo) * tanhf(cn);
            c_reg[it] = cn; cn_s[it] = cn; hn_s[it] = hn;
            bf16 hh = __float2bfloat16_rn(hn);
            bf16 hl = __float2bfloat16_rn(hn - __bfloat162float(hh));
            Adst[b * 2048 + j]        = hh;
            Adst[b * 2048 + 1024 + j] = hl;
        }

        // split-phase grid barrier: arrive
        __syncthreads();
        if (tid == 0) {
            __threadfence();
            unsigned old = atomicAdd(&g_bar_arrive, 1u);
            if (old == NB_ - 1u) {
                g_bar_arrive = 0;
                __threadfence();
                g_bar_gen = gen0 + t + 1;
            }
        }

        // overlap: output stores + next-step prefetch
#pragma unroll
        for (int it = 0; it < 2; it++) {
            int b = it ? bb2 : bb;
            if (LAYER == 1)
                out[(size_t)t * B_ * H_ + b * H_ + j] = hn_s[it];
            if (t == T_ - 1) {
                out[OUTS_ + (b * 2 + LAYER) * H_ + j] = hn_s[it];
                out[OUTS_ + 2 * B_ * H_ + (b * 2 + LAYER) * H_ + j] = cn_s[it];
            }
        }
        if (t + 1 < T_) {
            gp[0] = *(const float4*)&Gpre[((size_t)(t + 1) * B_ + bb) * G_ + n0 + 4 * jl];
            gp[1] = *(const float4*)&Gpre[((size_t)(t + 1) * B_ + bb2) * G_ + n0 + 4 * jl];
            rst[0] = reset[(t + 1) * B_ + bb];
            rst[1] = reset[(t + 1) * B_ + bb2];
        }

        // wait
        if (tid == 0) {
            while (ld_acq(&g_bar_gen) < gen0 + t + 1) { }
        }
        __syncthreads();
    }
}

__global__ __launch_bounds__(256, 1) void layer_kernel0(const int* __restrict__ reset, float* __restrict__ out)
{ layer_body<0>(reset, out); }
__global__ __launch_bounds__(256, 1) void layer_kernel1(const int* __restrict__ reset, float* __restrict__ out)
{ layer_body<1>(reset, out); }

// ---------------- launch ----------------
extern "C" void kernel_launch(void* const* d_in, const int* in_sizes, int n_in,
                              void* d_out, int out_size)
{
    (void)in_sizes; (void)n_in; (void)out_size;
    const float* input = (const float*)d_in[0];
    const int*   reset = (const int*)d_in[1];
    const float* h0    = (const float*)d_in[2];
    const float* c0    = (const float*)d_in[3];
    const float* Wi0   = (const float*)d_in[4];
    const float* Wh0   = (const float*)d_in[5];
    const float* bi0   = (const float*)d_in[6];
    const float* bh0   = (const float*)d_in[7];
    const float* Wi1   = (const float*)d_in[8];
    const float* Wh1   = (const float*)d_in[9];
    const float* bi1   = (const float*)d_in[10];
    const float* bh1   = (const float*)d_in[11];
    float* out = (float*)d_out;

    const int GEMM_SMEM  = 6 * 128 * GA_STR * 2;                          // 208896 B
    const int LAYER_SMEM = (32 * WSTR + 3 * 64 * ASTR) * 2 + 64 * 36 * 4; // 193024 B
    cudaFuncSetAttribute(gemm_kernel,   cudaFuncAttributeMaxDynamicSharedMemorySize, GEMM_SMEM);
    cudaFuncSetAttribute(layer_kernel0, cudaFuncAttributeMaxDynamicSharedMemorySize, LAYER_SMEM);
    cudaFuncSetAttribute(layer_kernel1, cudaFuncAttributeMaxDynamicSharedMemorySize, LAYER_SMEM);

    pack_hl_kernel<<<1024, 256>>>(Wi0,   0, G_,  D_);
    pack_hl_kernel<<<1024, 256>>>(Wh0,   1, G_,  H_);
    pack_hl_kernel<<<1024, 256>>>(Wi1,   2, G_,  H_);
    pack_hl_kernel<<<1024, 256>>>(Wh1,   3, G_,  H_);
    pack_hl_kernel<<<1024, 256>>>(input, 4, TB_, D_);
    bias_kernel<<<16, 256>>>(bi0, bh0, bi1, bh1);
    init_state_kernel<<<512, 256>>>(h0, c0);

    gemm_kernel<<<dim3(32, 128), 256, GEMM_SMEM>>>(0);   // G0
    layer_kernel0<<<NB_, 256, LAYER_SMEM>>>(reset, out); // layer 0
    gemm_kernel<<<dim3(32, 128), 256, GEMM_SMEM>>>(1);   // G1
    layer_kernel1<<<NB_, 256, LAYER_SMEM>>>(reset, out); // layer 1
}

// round 5
// speedup vs baseline: 2.2623x; 1.0004x over previous
#include <cuda_runtime.h>
#include <cuda_bf16.h>
#include <cstdint>
#include <cstddef>

typedef __nv_bfloat16 bf16;

#define T_ 256
#define B_ 64
#define D_ 512
#define H_ 1024
#define G_ 4096
#define TB_ (T_ * B_)
#define OUTS_ (TB_ * H_)
#define NB_ 128          // persistent grid size (layer kernels)

// ---------------- device scratch ----------------
__device__ bf16  g_Xp  [(size_t)TB_ * (2 * D_)];
__device__ bf16  g_Wi0p[(size_t)G_  * (2 * D_)];
__device__ bf16  g_Wh0p[(size_t)G_  * (2 * H_)];
__device__ bf16  g_Wi1p[(size_t)G_  * (2 * H_)];
__device__ bf16  g_Wh1p[(size_t)G_  * (2 * H_)];
__device__ float g_b0[G_], g_b1[G_];
__device__ float g_G0[(size_t)TB_ * G_];
__device__ float g_G1[(size_t)TB_ * G_];
__device__ float g_c0s[2 * B_ * H_];
__device__ bf16  g_X1p[(size_t)(T_ + 1) * B_ * 2 * H_];
__device__ bf16  g_h1p[2][B_ * 2 * H_];
__device__ unsigned g_bar_grp[8];    // zero-init
__device__ unsigned g_bar_root;      // zero-init
__device__ unsigned g_bar_gen;      // zero-init, monotonic

// ---------------- helpers ----------------
__device__ __forceinline__ void cp_async16(void* sdst, const void* gsrc) {
    uint32_t s = (uint32_t)__cvta_generic_to_shared(sdst);
    asm volatile("cp.async.cg.shared.global [%0], [%1], 16;\n" :: "r"(s), "l"(gsrc));
}
__device__ __forceinline__ void cp_commit() { asm volatile("cp.async.commit_group;\n"); }
template <int N> __device__ __forceinline__ void cp_wait() {
    asm volatile("cp.async.wait_group %0;\n" :: "n"(N));
}
__device__ __forceinline__ unsigned ld_acq(const unsigned* p) {
    unsigned v; asm volatile("ld.acquire.gpu.u32 %0, [%1];" : "=r"(v) : "l"(p)); return v;
}
__device__ __forceinline__ void mma16816(float* d,
    uint32_t a0, uint32_t a1, uint32_t a2, uint32_t a3, uint32_t b0, uint32_t b1)
{
    asm volatile(
        "mma.sync.aligned.m16n8k16.row.col.f32.bf16.bf16.f32 "
        "{%0,%1,%2,%3},{%4,%5,%6,%7},{%8,%9},{%0,%1,%2,%3};\n"
        : "+f"(d[0]), "+f"(d[1]), "+f"(d[2]), "+f"(d[3])
        : "r"(a0), "r"(a1), "r"(a2), "r"(a3), "r"(b0), "r"(b1));
}
__device__ __forceinline__ void ldsm4(uint32_t& a, uint32_t& b, uint32_t& c, uint32_t& d,
                                      uint32_t addr)
{
    asm volatile("ldmatrix.sync.aligned.m8n8.x4.shared.b16 {%0,%1,%2,%3}, [%4];"
        : "=r"(a), "=r"(b), "=r"(c), "=r"(d) : "r"(addr));
}
__device__ __forceinline__ float sigmoidf_(float z) { return 1.f / (1.f + __expf(-z)); }

// ---------------- packing (float4 vectorized) ----------------
__global__ void pack_hl_kernel(const float* __restrict__ src, int which, int rows, int K)
{
    bf16* dst = (which == 0) ? g_Wi0p : (which == 1) ? g_Wh0p :
                (which == 2) ? g_Wi1p : (which == 3) ? g_Wh1p : g_Xp;
    bool perm = (which < 4);
    int K4 = K >> 2;
    int total = rows * K4;
    for (int id = blockIdx.x * blockDim.x + threadIdx.x; id < total;
         id += gridDim.x * blockDim.x) {
        int r = id / K4, k4 = (id - r * K4) * 4;
        int sr = perm ? ((r & 3) * H_ + (r >> 2)) : r;
        float4 v = *(const float4*)&src[(size_t)sr * K + k4];
        bf16 h0 = __float2bfloat16_rn(v.x), h1 = __float2bfloat16_rn(v.y);
        bf16 h2 = __float2bfloat16_rn(v.z), h3 = __float2bfloat16_rn(v.w);
        bf16 l0 = __float2bfloat16_rn(v.x - __bfloat162float(h0));
        bf16 l1 = __float2bfloat16_rn(v.y - __bfloat162float(h1));
        bf16 l2 = __float2bfloat16_rn(v.z - __bfloat162float(h2));
        bf16 l3 = __float2bfloat16_rn(v.w - __bfloat162float(h3));
        __nv_bfloat162 hv0 = {h0, h1}, hv1 = {h2, h3}, lv0 = {l0, l1}, lv1 = {l2, l3};
        *(uint2*)&dst[(size_t)r * (2 * K) + k4]     = make_uint2(*(uint32_t*)&hv0, *(uint32_t*)&hv1);
        *(uint2*)&dst[(size_t)r * (2 * K) + K + k4] = make_uint2(*(uint32_t*)&lv0, *(uint32_t*)&lv1);
    }
}

__global__ void bias_kernel(const float* __restrict__ bi0, const float* __restrict__ bh0,
                            const float* __restrict__ bi1, const float* __restrict__ bh1)
{
    int r = blockIdx.x * blockDim.x + threadIdx.x;
    if (r < G_) {
        int sr = (r & 3) * H_ + (r >> 2);
        g_b0[r] = bi0[sr] + bh0[sr];
        g_b1[r] = bi1[sr] + bh1[sr];
    }
}

__global__ void init_state_kernel(const float* __restrict__ h0, const float* __restrict__ c0)
{
    int id = blockIdx.x * blockDim.x + threadIdx.x;
    if (id < 2 * B_ * H_) {
        int l = id / (B_ * H_);
        int b = (id / H_) % B_;
        int j = id % H_;
        float hv = h0[(b * 2 + l) * H_ + j];
        g_c0s[id] = c0[(b * 2 + l) * H_ + j];
        bf16 hh = __float2bfloat16_rn(hv);
        bf16 hl = __float2bfloat16_rn(hv - __bfloat162float(hh));
        if (l == 0) {
            g_X1p[b * 2048 + j]        = hh;
            g_X1p[b * 2048 + 1024 + j] = hl;
        } else {
            g_h1p[0][b * 2048 + j]        = hh;
            g_h1p[0][b * 2048 + 1024 + j] = hl;
        }
    }
}

// ---------------- big GEMM: out = A @ B^T + bias (mma.sync + ldmatrix) ----------------
// CTA tile 128x128, 256 threads (8 warps 2(M) x 4(N), warp tile 64x32),
// K-chunk 64, 3-stage cp.async ring, one __syncthreads per chunk.
#define GA_STR 136
__global__ __launch_bounds__(256) void gemm_kernel(int sel)
{
    extern __shared__ bf16 sm[];
    const int AS = 128 * GA_STR;
    bf16* sA = sm;             // 3 stages
    bf16* sB = sm + 3 * AS;    // 3 stages
    uint32_t sA_u = (uint32_t)__cvta_generic_to_shared(sA);
    uint32_t sB_u = (uint32_t)__cvta_generic_to_shared(sB);

    const bf16 *A, *B; const float* bias; float* outp; int K;
    if (sel == 0) { A = g_Xp;  B = g_Wi0p; bias = g_b0; outp = g_G0; K = 512; }
    else { A = g_X1p + (size_t)B_ * 2048; B = g_Wi1p; bias = g_b1; outp = g_G1; K = 1024; }

    int tid = threadIdx.x, w = tid >> 5, lane = tid & 31, g = lane >> 2, t4 = lane & 3;
    int wm = w & 1, wn = w >> 1;
    int m0 = blockIdx.y * 128, n0 = blockIdx.x * 128;
    int rs = 2 * K;
    int NC = K / 64;

    // ldmatrix per-lane bases (byte offsets within a stage)
    int lr = lane & 15;
    int lcA = (lane >> 4) * 8;
    uint32_t aBase[4], bBase[2];
#pragma unroll
    for (int mt = 0; mt < 4; mt++)
        aBase[mt] = (uint32_t)(((wm * 64 + mt * 16 + lr) * GA_STR + lcA) * 2);
#pragma unroll
    for (int p = 0; p < 2; p++)
        bBase[p] = (uint32_t)(((wn * 32 + p * 16 + (lane & 7) + ((lane >> 4) & 1) * 8) * GA_STR
                               + ((lane >> 3) & 1) * 8) * 2);

    float acc[4][4][4];
#pragma unroll
    for (int a = 0; a < 4; a++)
#pragma unroll
        for (int b = 0; b < 4; b++)
#pragma unroll
            for (int c = 0; c < 4; c++) acc[a][b][c] = 0.f;

    auto issue = [&](int c) {
        int k0 = c * 64;
        int st = c % 3;
#pragma unroll
        for (int v = 0; v < 8; v++) {
            int idx = tid + v * 256;
            int r = idx >> 4, s = idx & 15;
            int src = (s < 8) ? (k0 + s * 8) : (K + k0 + (s - 8) * 8);
            cp_async16(&sA[st * AS + r * GA_STR + s * 8], &A[(size_t)(m0 + r) * rs + src]);
        }
#pragma unroll
        for (int v = 0; v < 8; v++) {
            int idx = tid + v * 256;
            int r = idx >> 4, s = idx & 15;
            int src = (s < 8) ? (k0 + s * 8) : (K + k0 + (s - 8) * 8);
            cp_async16(&sB[st * AS + r * GA_STR + s * 8], &B[(size_t)(n0 + r) * rs + src]);
        }
        cp_commit();
    };

    issue(0); issue(1);
    for (int c = 0; c < NC; c++) {
        if (c + 1 < NC) cp_wait<1>(); else cp_wait<0>();
        __syncthreads();
        if (c + 2 < NC) issue(c + 2);
        uint32_t stA = sA_u + (uint32_t)((c % 3) * AS * 2);
        uint32_t stB = sB_u + (uint32_t)((c % 3) * AS * 2);
#pragma unroll
        for (int kk = 0; kk < 4; kk++) {
            uint32_t kbb = (uint32_t)(kk * 32);   // 16 elems * 2B
            uint32_t Ah[4][4], Al[4][4], Bh[4][2], Bl[4][2];
#pragma unroll
            for (int mt = 0; mt < 4; mt++) {
                ldsm4(Ah[mt][0], Ah[mt][1], Ah[mt][2], Ah[mt][3], stA + aBase[mt] + kbb);
                ldsm4(Al[mt][0], Al[mt][1], Al[mt][2], Al[mt][3], stA + aBase[mt] + 128 + kbb);
            }
#pragma unroll
            for (int p = 0; p < 2; p++) {
                ldsm4(Bh[2 * p][0], Bh[2 * p][1], Bh[2 * p + 1][0], Bh[2 * p + 1][1],
                      stB + bBase[p] + kbb);
                ldsm4(Bl[2 * p][0], Bl[2 * p][1], Bl[2 * p + 1][0], Bl[2 * p + 1][1],
                      stB + bBase[p] + 128 + kbb);
            }
#pragma unroll
            for (int mt = 0; mt < 4; mt++)
#pragma unroll
                for (int nt = 0; nt < 4; nt++) {
                    mma16816(acc[mt][nt], Ah[mt][0], Ah[mt][1], Ah[mt][2], Ah[mt][3], Bh[nt][0], Bh[nt][1]);
                    mma16816(acc[mt][nt], Al[mt][0], Al[mt][1], Al[mt][2], Al[mt][3], Bh[nt][0], Bh[nt][1]);
                    mma16816(acc[mt][nt], Ah[mt][0], Ah[mt][1], Ah[mt][2], Ah[mt][3], Bl[nt][0], Bl[nt][1]);
                }
        }
    }

#pragma unroll
    for (int mt = 0; mt < 4; mt++)
#pragma unroll
        for (int nt = 0; nt < 4; nt++) {
            int row = m0 + wm * 64 + mt * 16 + g;
            int col = n0 + wn * 32 + nt * 8 + 2 * t4;
            float ba = bias[col], bb = bias[col + 1];
            *(float2*)&outp[(size_t)row * G_ + col] =
                make_float2(acc[mt][nt][0] + ba, acc[mt][nt][1] + bb);
            *(float2*)&outp[(size_t)(row + 8) * G_ + col] =
                make_float2(acc[mt][nt][2] + ba, acc[mt][nt][3] + bb);
        }
}

// ---------------- persistent layer kernel (mma.sync + ldmatrix) ----------------
#define WSTR 2056
#define ASTR 136

template <int LAYER>
__device__ __forceinline__ void layer_body(const int* __restrict__ reset, float* __restrict__ out)
{
    extern __shared__ bf16 smem[];
    bf16* sW = smem;                           // 32 x WSTR
    bf16* sA = smem + 32 * WSTR;               // 3 x 64 x ASTR
    float* zs = (float*)(sA + 3 * 64 * ASTR);  // 64 x 36
    uint32_t sW_u = (uint32_t)__cvta_generic_to_shared(sW);
    uint32_t sA_u = (uint32_t)__cvta_generic_to_shared(sA);

    int tid = threadIdx.x, w = tid >> 5, lane = tid & 31, g = lane >> 2, t4 = lane & 3;
    int wm = w & 1, wn = w >> 1;
    int n0 = blockIdx.x * 32;
    unsigned gen0 = ld_acq(&g_bar_gen);

    const bf16* Wsrc = (LAYER == 0 ? g_Wh0p : g_Wh1p) + (size_t)n0 * 2048;
    for (int i = tid; i < 32 * 256; i += 256) {
        int r = i >> 8, s = i & 255;
        *(uint4*)&sW[r * WSTR + s * 8] = *(const uint4*)&Wsrc[(size_t)r * 2048 + s * 8];
    }

    const float* Gpre = (LAYER == 0) ? g_G0 : g_G1;

    // ldmatrix per-lane bases
    int lr = lane & 15;
    int lcA = (lane >> 4) * 8;
    uint32_t aBase[2];
    aBase[0] = (uint32_t)(((wm * 32 + 0 + lr) * ASTR + lcA) * 2);
    aBase[1] = (uint32_t)(((wm * 32 + 16 + lr) * ASTR + lcA) * 2);
    // B x4: {b0h, b1h, b0l, b1l}: col add = 8*((lane>>3)&1) + 1024*((lane>>4)&1)
    uint32_t bBase = (uint32_t)(((wn * 8 + (lane & 7)) * WSTR
                                 + ((lane >> 3) & 1) * 8 + ((lane >> 4) & 1) * 1024) * 2);

    int bb = tid >> 3, jl = tid & 7, j = blockIdx.x * 8 + jl;
    int bb2 = (tid + 256) >> 3;

    float c_reg[2];
    c_reg[0] = g_c0s[(LAYER * B_ + bb) * H_ + j];
    c_reg[1] = g_c0s[(LAYER * B_ + bb2) * H_ + j];

    float4 gp[2]; int rst[2];
    gp[0] = *(const float4*)&Gpre[(size_t)bb * G_ + n0 + 4 * jl];
    gp[1] = *(const float4*)&Gpre[(size_t)bb2 * G_ + n0 + 4 * jl];
    rst[0] = reset[bb];
    rst[1] = reset[bb2];
    __syncthreads();

    for (int t = 0; t < T_; t++) {
        const bf16* Asrc = (LAYER == 0) ? (g_X1p + (size_t)t * B_ * 2048) : g_h1p[t & 1];
        bf16* Adst = (LAYER == 0) ? (g_X1p + (size_t)(t + 1) * B_ * 2048) : g_h1p[(t + 1) & 1];

        float acc[2][4];
#pragma unroll
        for (int a = 0; a < 2; a++)
#pragma unroll
            for (int c = 0; c < 4; c++) acc[a][c] = 0.f;

        auto issue = [&](int c) {
            int k0 = c * 64, st = c % 3;
#pragma unroll
            for (int v = 0; v < 4; v++) {
                int idx = tid + v * 256;
                int r = idx >> 4, s = idx & 15;
                int src = (s < 8) ? (k0 + s * 8) : (1024 + k0 + (s - 8) * 8);
                cp_async16(&sA[st * 64 * ASTR + r * ASTR + s * 8], &Asrc[(size_t)r * 2048 + src]);
            }
            cp_commit();
        };

        issue(0); issue(1);
        for (int c = 0; c < 16; c++) {
            if (c + 1 < 16) cp_wait<1>(); else cp_wait<0>();
            __syncthreads();
            if (c + 2 < 16) issue(c + 2);
            uint32_t stA = sA_u + (uint32_t)((c % 3) * 64 * ASTR * 2);
            uint32_t wOff = (uint32_t)(c * 64 * 2);   // k0 * 2 bytes
#pragma unroll
            for (int kk = 0; kk < 4; kk++) {
                uint32_t kbb = (uint32_t)(kk * 32);
                uint32_t Ah[2][4], Al[2][4], Bq[4];
#pragma unroll
                for (int mt = 0; mt < 2; mt++) {
                    ldsm4(Ah[mt][0], Ah[mt][1], Ah[mt][2], Ah[mt][3], stA + aBase[mt] + kbb);
                    ldsm4(Al[mt][0], Al[mt][1], Al[mt][2], Al[mt][3], stA + aBase[mt] + 128 + kbb);
                }
                ldsm4(Bq[0], Bq[1], Bq[2], Bq[3], sW_u + bBase + wOff + kbb);
#pragma unroll
                for (int mt = 0; mt < 2; mt++) {
                    mma16816(acc[mt], Ah[mt][0], Ah[mt][1], Ah[mt][2], Ah[mt][3], Bq[0], Bq[1]);
                    mma16816(acc[mt], Al[mt][0], Al[mt][1], Al[mt][2], Al[mt][3], Bq[0], Bq[1]);
                    mma16816(acc[mt], Ah[mt][0], Ah[mt][1], Ah[mt][2], Ah[mt][3], Bq[2], Bq[3]);
                }
            }
        }

        __syncthreads();
#pragma unroll
        for (int mt = 0; mt < 2; mt++) {
            int r0 = wm * 32 + mt * 16 + g;
            int c0 = wn * 8 + 2 * t4;
            zs[r0 * 36 + c0]     = acc[mt][0];
            zs[r0 * 36 + c0 + 1] = acc[mt][1];
            zs[(r0 + 8) * 36 + c0]     = acc[mt][2];
            zs[(r0 + 8) * 36 + c0 + 1] = acc[mt][3];
        }
        __syncthreads();

        float hn_s[2], cn_s[2];
#pragma unroll
        for (int it = 0; it < 2; it++) {
            int b = it ? bb2 : bb;
            float keep = 1.0f - (float)rst[it];
            float zi = gp[it].x + keep * zs[b * 36 + 4 * jl + 0];
            float zf = gp[it].y + keep * zs[b * 36 + 4 * jl + 1];
            float zg = gp[it].z + keep * zs[b * 36 + 4 * jl + 2];
            float zo = gp[it].w + keep * zs[b * 36 + 4 * jl + 3];
            float cn = sigmoidf_(zf) * keep * c_reg[it] + sigmoidf_(zi) * tanhf(zg);
            float hn = sigmoidf_(zo) * tanhf(cn);
            c_reg[it] = cn; cn_s[it] = cn; hn_s[it] = hn;
            bf16 hh = __float2bfloat16_rn(hn);
            bf16 hl = __float2bfloat16_rn(hn - __bfloat162float(hh));
            Adst[b * 2048 + j]        = hh;
            Adst[b * 2048 + 1024 + j] = hl;
        }

        // split-phase two-level grid barrier: arrive
        __syncthreads();
        if (tid == 0) {
            __threadfence();
            unsigned grp = (unsigned)blockIdx.x >> 4;
            if (atomicAdd(&g_bar_grp[grp], 1u) == 15u) {
                g_bar_grp[grp] = 0u;
                if (atomicAdd(&g_bar_root, 1u) == 7u) {
                    g_bar_root = 0u;
                    __threadfence();
                    g_bar_gen = gen0 + t + 1;
                }
            }
        }

        // overlap: output stores + next-step prefetch
#pragma unroll
        for (int it = 0; it < 2; it++) {
            int b = it ? bb2 : bb;
            if (LAYER == 1)
                out[(size_t)t * B_ * H_ + b * H_ + j] = hn_s[it];
            if (t == T_ - 1) {
                out[OUTS_ + (b * 2 + LAYER) * H_ + j] = hn_s[it];
                out[OUTS_ + 2 * B_ * H_ + (b * 2 + LAYER) * H_ + j] = cn_s[it];
            }
        }
        if (t + 1 < T_) {
            gp[0] = *(const float4*)&Gpre[((size_t)(t + 1) * B_ + bb) * G_ + n0 + 4 * jl];
            gp[1] = *(const float4*)&Gpre[((size_t)(t + 1) * B_ + bb2) * G_ + n0 + 4 * jl];
            rst[0] = reset[(t + 1) * B_ + bb];
            rst[1] = reset[(t + 1) * B_ + bb2];
        }

        if (tid == 0) {
            while (ld_acq(&g_bar_gen) < gen0 + t + 1) { }
        }
        __syncthreads();
    }
}

__global__ __launch_bounds__(256, 1) void layer_kernel0(const int* __restrict__ reset, float* __restrict__ out)
{ layer_body<0>(reset, out); }
__global__ __launch_bounds__(256, 1) void layer_kernel1(const int* __restrict__ reset, float* __restrict__ out)
{ layer_body<1>(reset, out); }

// ---------------- launch ----------------
extern "C" void kernel_launch(void* const* d_in, const int* in_sizes, int n_in,
                              void* d_out, int out_size)
{
    (void)in_sizes; (void)n_in; (void)out_size;
    const float* input = (const float*)d_in[0];
    const int*   reset = (const int*)d_in[1];
    const float* h0    = (const float*)d_in[2];
    const float* c0    = (const float*)d_in[3];
    const float* Wi0   = (const float*)d_in[4];
    const float* Wh0   = (const float*)d_in[5];
    const float* bi0   = (const float*)d_in[6];
    const float* bh0   = (const float*)d_in[7];
    const float* Wi1   = (const float*)d_in[8];
    const float* Wh1   = (const float*)d_in[9];
    const float* bi1   = (const float*)d_in[10];
    const float* bh1   = (const float*)d_in[11];
    float* out = (float*)d_out;

    const int GEMM_SMEM  = 6 * 128 * GA_STR * 2;                          // 208896 B
    const int LAYER_SMEM = (32 * WSTR + 3 * 64 * ASTR) * 2 + 64 * 36 * 4; // 193024 B
    cudaFuncSetAttribute(gemm_kernel,   cudaFuncAttributeMaxDynamicSharedMemorySize, GEMM_SMEM);
    cudaFuncSetAttribute(layer_kernel0, cudaFuncAttributeMaxDynamicSharedMemorySize, LAYER_SMEM);
    cudaFuncSetAttribute(layer_kernel1, cudaFuncAttributeMaxDynamicSharedMemorySize, LAYER_SMEM);

    pack_hl_kernel<<<1024, 256>>>(Wi0,   0, G_,  D_);
    pack_hl_kernel<<<1024, 256>>>(Wh0,   1, G_,  H_);
    pack_hl_kernel<<<1024, 256>>>(Wi1,   2, G_,  H_);
    pack_hl_kernel<<<1024, 256>>>(Wh1,   3, G_,  H_);
    pack_hl_kernel<<<1024, 256>>>(input, 4, TB_, D_);
    bias_kernel<<<16, 256>>>(bi0, bh0, bi1, bh1);
    init_state_kernel<<<512, 256>>>(h0, c0);

    gemm_kernel<<<dim3(32, 128), 256, GEMM_SMEM>>>(0);   // G0
    layer_kernel0<<<NB_, 256, LAYER_SMEM>>>(reset, out); // layer 0
    gemm_kernel<<<dim3(32, 128), 256, GEMM_SMEM>>>(1);   // G1
    layer_kernel1<<<NB_, 256, LAYER_SMEM>>>(reset, out); // layer 1
}

// round 6
// speedup vs baseline: 3.3644x; 1.4871x over previous
#include <cuda_runtime.h>
#include <cuda_fp16.h>
#include <cstdint>
#include <cstddef>

typedef __half f16;

#define T_ 256
#define B_ 64
#define D_ 512
#define H_ 1024
#define G_ 4096
#define TB_ (T_ * B_)
#define OUTS_ (TB_ * H_)
#define NB_ 128          // persistent grid size (layer kernels)

// ---------------- device scratch ----------------
__device__ f16   g_Xp  [(size_t)TB_ * D_];         // input, single fp16, stride 512
__device__ f16   g_Wi0p[(size_t)G_  * (2 * D_)];   // W hi|lo, stride 1024
__device__ f16   g_Wh0p[(size_t)G_  * (2 * H_)];   // stride 2048
__device__ f16   g_Wi1p[(size_t)G_  * (2 * H_)];
__device__ f16   g_Wh1p[(size_t)G_  * (2 * H_)];
__device__ float g_b0[G_], g_b1[G_];
__device__ float g_G0[(size_t)TB_ * G_];
__device__ float g_G1[(size_t)TB_ * G_];
__device__ float g_c0s[2 * B_ * H_];
__device__ f16   g_X1p[(size_t)(T_ + 1) * B_ * H_];  // single fp16, stride 1024
__device__ f16   g_h1p[2][B_ * H_];
__device__ unsigned g_bar_grp[8];    // zero-init
__device__ unsigned g_bar_root;      // zero-init
__device__ unsigned g_bar_gen;       // zero-init, monotonic

// ---------------- helpers ----------------
__device__ __forceinline__ void cp_async16(void* sdst, const void* gsrc) {
    uint32_t s = (uint32_t)__cvta_generic_to_shared(sdst);
    asm volatile("cp.async.cg.shared.global [%0], [%1], 16;\n" :: "r"(s), "l"(gsrc));
}
__device__ __forceinline__ void cp_commit() { asm volatile("cp.async.commit_group;\n"); }
template <int N> __device__ __forceinline__ void cp_wait() {
    asm volatile("cp.async.wait_group %0;\n" :: "n"(N));
}
__device__ __forceinline__ unsigned ld_acq(const unsigned* p) {
    unsigned v; asm volatile("ld.acquire.gpu.u32 %0, [%1];" : "=r"(v) : "l"(p)); return v;
}
__device__ __forceinline__ void mma16816(float* d,
    uint32_t a0, uint32_t a1, uint32_t a2, uint32_t a3, uint32_t b0, uint32_t b1)
{
    asm volatile(
        "mma.sync.aligned.m16n8k16.row.col.f32.f16.f16.f32 "
        "{%0,%1,%2,%3},{%4,%5,%6,%7},{%8,%9},{%0,%1,%2,%3};\n"
        : "+f"(d[0]), "+f"(d[1]), "+f"(d[2]), "+f"(d[3])
        : "r"(a0), "r"(a1), "r"(a2), "r"(a3), "r"(b0), "r"(b1));
}
__device__ __forceinline__ void ldsm4(uint32_t& a, uint32_t& b, uint32_t& c, uint32_t& d,
                                      uint32_t addr)
{
    asm volatile("ldmatrix.sync.aligned.m8n8.x4.shared.b16 {%0,%1,%2,%3}, [%4];"
        : "=r"(a), "=r"(b), "=r"(c), "=r"(d) : "r"(addr));
}
__device__ __forceinline__ float sigmoidf_(float z) { return 1.f / (1.f + __expf(-z)); }

// ---------------- packing ----------------
// weights: hi/lo fp16, gate-row permuted, dst row = [hi K | lo K], stride 2K
__global__ void pack_w_kernel(const float* __restrict__ src, int which, int K)
{
    f16* dst = (which == 0) ? g_Wi0p : (which == 1) ? g_Wh0p :
               (which == 2) ? g_Wi1p : g_Wh1p;
    int K4 = K >> 2;
    int total = G_ * K4;
    for (int id = blockIdx.x * blockDim.x + threadIdx.x; id < total;
         id += gridDim.x * blockDim.x) {
        int r = id / K4, k4 = (id - r * K4) * 4;
        int sr = (r & 3) * H_ + (r >> 2);
        float4 v = *(const float4*)&src[(size_t)sr * K + k4];
        f16 h0 = __float2half_rn(v.x), h1 = __float2half_rn(v.y);
        f16 h2 = __float2half_rn(v.z), h3 = __float2half_rn(v.w);
        f16 l0 = __float2half_rn(v.x - __half2float(h0));
        f16 l1 = __float2half_rn(v.y - __half2float(h1));
        f16 l2 = __float2half_rn(v.z - __half2float(h2));
        f16 l3 = __float2half_rn(v.w - __half2float(h3));
        __half2 hv0 = {h0, h1}, hv1 = {h2, h3}, lv0 = {l0, l1}, lv1 = {l2, l3};
        *(uint2*)&dst[(size_t)r * (2 * K) + k4]     = make_uint2(*(uint32_t*)&hv0, *(uint32_t*)&hv1);
        *(uint2*)&dst[(size_t)r * (2 * K) + K + k4] = make_uint2(*(uint32_t*)&lv0, *(uint32_t*)&lv1);
    }
}

// input: single fp16, stride 512
__global__ void pack_x_kernel(const float* __restrict__ src)
{
    int total = TB_ * (D_ >> 2);
    for (int id = blockIdx.x * blockDim.x + threadIdx.x; id < total;
         id += gridDim.x * blockDim.x) {
        int r = id / (D_ >> 2), k4 = (id - r * (D_ >> 2)) * 4;
        float4 v = *(const float4*)&src[(size_t)r * D_ + k4];
        __half2 a = {__float2half_rn(v.x), __float2half_rn(v.y)};
        __half2 b = {__float2half_rn(v.z), __float2half_rn(v.w)};
        *(uint2*)&g_Xp[(size_t)r * D_ + k4] = make_uint2(*(uint32_t*)&a, *(uint32_t*)&b);
    }
}

__global__ void bias_kernel(const float* __restrict__ bi0, const float* __restrict__ bh0,
                            const float* __restrict__ bi1, const float* __restrict__ bh1)
{
    int r = blockIdx.x * blockDim.x + threadIdx.x;
    if (r < G_) {
        int sr = (r & 3) * H_ + (r >> 2);
        g_b0[r] = bi0[sr] + bh0[sr];
        g_b1[r] = bi1[sr] + bh1[sr];
    }
}

__global__ void init_state_kernel(const float* __restrict__ h0, const float* __restrict__ c0)
{
    int id = blockIdx.x * blockDim.x + threadIdx.x;
    if (id < 2 * B_ * H_) {
        int l = id / (B_ * H_);
        int b = (id / H_) % B_;
        int j = id % H_;
        float hv = h0[(b * 2 + l) * H_ + j];
        g_c0s[id] = c0[(b * 2 + l) * H_ + j];
        f16 hh = __float2half_rn(hv);
        if (l == 0) g_X1p[b * H_ + j] = hh;        // slot 0
        else        g_h1p[0][b * H_ + j] = hh;
    }
}

// ---------------- big GEMM: out = A @ B^T + bias (2-product fp16) ----------------
// A: M x K single fp16.  B: 4096 x 2K (hi|lo).  out fp32.
// CTA tile 128x128, 256 threads (8 warps 2(M) x 4(N), warp tile 64x32),
// K-chunk 64, 3-stage cp.async ring.
#define GAS 72     // A stage row stride (64 cols + 8 pad)
#define GBS 136    // B stage row stride (64 hi + 64 lo + 8 pad)
__global__ __launch_bounds__(256) void gemm_kernel(int sel)
{
    extern __shared__ f16 sm[];
    const int AS = 128 * GAS;
    const int BS = 128 * GBS;
    f16* sA = sm;              // 3 stages
    f16* sB = sm + 3 * AS;     // 3 stages
    uint32_t sA_u = (uint32_t)__cvta_generic_to_shared(sA);
    uint32_t sB_u = (uint32_t)__cvta_generic_to_shared(sB);

    const f16 *A, *B; const float* bias; float* outp; int K;
    if (sel == 0) { A = g_Xp;  B = g_Wi0p; bias = g_b0; outp = g_G0; K = 512; }
    else { A = g_X1p + (size_t)B_ * H_; B = g_Wi1p; bias = g_b1; outp = g_G1; K = 1024; }

    int tid = threadIdx.x, w = tid >> 5, lane = tid & 31, g = lane >> 2, t4 = lane & 3;
    int wm = w & 1, wn = w >> 1;
    int m0 = blockIdx.y * 128, n0 = blockIdx.x * 128;
    int NC = K / 64;

    // ldmatrix per-lane bases (byte offsets within a stage)
    int lr = lane & 15;
    int lcA = (lane >> 4) * 8;
    uint32_t aBase[4], bBase[2];
#pragma unroll
    for (int mt = 0; mt < 4; mt++)
        aBase[mt] = (uint32_t)(((wm * 64 + mt * 16 + lr) * GAS + lcA) * 2);
#pragma unroll
    for (int p = 0; p < 2; p++)
        bBase[p] = (uint32_t)(((wn * 32 + p * 16 + (lane & 7) + ((lane >> 4) & 1) * 8) * GBS
                               + ((lane >> 3) & 1) * 8) * 2);

    float acc[4][4][4];
#pragma unroll
    for (int a = 0; a < 4; a++)
#pragma unroll
        for (int b = 0; b < 4; b++)
#pragma unroll
            for (int c = 0; c < 4; c++) acc[a][b][c] = 0.f;

    auto issue = [&](int c) {
        int k0 = c * 64;
        int st = c % 3;
#pragma unroll
        for (int v = 0; v < 4; v++) {           // A: 128 rows x 8 segs
            int idx = tid + v * 256;
            int r = idx >> 3, s = idx & 7;
            cp_async16(&sA[st * AS + r * GAS + s * 8], &A[(size_t)(m0 + r) * K + k0 + s * 8]);
        }
#pragma unroll
        for (int v = 0; v < 8; v++) {           // B: 128 rows x 16 segs (hi|lo)
            int idx = tid + v * 256;
            int r = idx >> 4, s = idx & 15;
            int src = (s < 8) ? (k0 + s * 8) : (K + k0 + (s - 8) * 8);
            cp_async16(&sB[st * BS + r * GBS + s * 8], &B[(size_t)(n0 + r) * (2 * K) + src]);
        }
        cp_commit();
    };

    issue(0); issue(1);
    for (int c = 0; c < NC; c++) {
        if (c + 1 < NC) cp_wait<1>(); else cp_wait<0>();
        __syncthreads();
        if (c + 2 < NC) issue(c + 2);
        uint32_t stA = sA_u + (uint32_t)((c % 3) * AS * 2);
        uint32_t stB = sB_u + (uint32_t)((c % 3) * BS * 2);
#pragma unroll
        for (int kk = 0; kk < 4; kk++) {
            uint32_t kbb = (uint32_t)(kk * 32);   // 16 elems * 2B
            uint32_t Aa[4][4], Bh[4][2], Bl[4][2];
#pragma unroll
            for (int mt = 0; mt < 4; mt++)
                ldsm4(Aa[mt][0], Aa[mt][1], Aa[mt][2], Aa[mt][3], stA + aBase[mt] + kbb);
#pragma unroll
            for (int p = 0; p < 2; p++) {
                ldsm4(Bh[2 * p][0], Bh[2 * p][1], Bh[2 * p + 1][0], Bh[2 * p + 1][1],
                      stB + bBase[p] + kbb);
                ldsm4(Bl[2 * p][0], Bl[2 * p][1], Bl[2 * p + 1][0], Bl[2 * p + 1][1],
                      stB + bBase[p] + 128 + kbb);
            }
#pragma unroll
            for (int mt = 0; mt < 4; mt++)
#pragma unroll
                for (int nt = 0; nt < 4; nt++) {
                    mma16816(acc[mt][nt], Aa[mt][0], Aa[mt][1], Aa[mt][2], Aa[mt][3], Bh[nt][0], Bh[nt][1]);
                    mma16816(acc[mt][nt], Aa[mt][0], Aa[mt][1], Aa[mt][2], Aa[mt][3], Bl[nt][0], Bl[nt][1]);
                }
        }
    }

#pragma unroll
    for (int mt = 0; mt < 4; mt++)
#pragma unroll
        for (int nt = 0; nt < 4; nt++) {
            int row = m0 + wm * 64 + mt * 16 + g;
            int col = n0 + wn * 32 + nt * 8 + 2 * t4;
            float ba = bias[col], bb = bias[col + 1];
            *(float2*)&outp[(size_t)row * G_ + col] =
                make_float2(acc[mt][nt][0] + ba, acc[mt][nt][1] + bb);
            *(float2*)&outp[(size_t)(row + 8) * G_ + col] =
                make_float2(acc[mt][nt][2] + ba, acc[mt][nt][3] + bb);
        }
}

// ---------------- persistent layer kernel (2-product fp16) ----------------
// A single fp16 (stride 1024), W hi|lo slice in SMEM. Chunk 128 cols, 8 chunks, 4-stage ring.
#define WSTR 2056   // 1024 hi + 1024 lo + 8 pad
#define ASTR 136    // 128 cols + 8 pad

template <int LAYER>
__device__ __forceinline__ void layer_body(const int* __restrict__ reset, float* __restrict__ out)
{
    extern __shared__ f16 smem[];
    f16* sW = smem;                             // 32 x WSTR
    f16* sA = smem + 32 * WSTR;                 // 4 x 64 x ASTR
    float* zs = (float*)(sA + 4 * 64 * ASTR);   // 64 x 36
    uint32_t sW_u = (uint32_t)__cvta_generic_to_shared(sW);
    uint32_t sA_u = (uint32_t)__cvta_generic_to_shared(sA);

    int tid = threadIdx.x, w = tid >> 5, lane = tid & 31, g = lane >> 2, t4 = lane & 3;
    int wm = w & 1, wn = w >> 1;
    int n0 = blockIdx.x * 32;
    unsigned gen0 = ld_acq(&g_bar_gen);

    const f16* Wsrc = (LAYER == 0 ? g_Wh0p : g_Wh1p) + (size_t)n0 * 2048;
    for (int i = tid; i < 32 * 256; i += 256) {
        int r = i >> 8, s = i & 255;
        *(uint4*)&sW[r * WSTR + s * 8] = *(const uint4*)&Wsrc[(size_t)r * 2048 + s * 8];
    }

    const float* Gpre = (LAYER == 0) ? g_G0 : g_G1;

    // ldmatrix per-lane bases
    int lr = lane & 15;
    int lcA = (lane >> 4) * 8;
    uint32_t aBase[2];
    aBase[0] = (uint32_t)(((wm * 32 + 0 + lr) * ASTR + lcA) * 2);
    aBase[1] = (uint32_t)(((wm * 32 + 16 + lr) * ASTR + lcA) * 2);
    // W x4: {bh0, bh1, bl0, bl1}: rows wn*8+(lane&7); +8 elems for k-half; +1024 elems for lo
    uint32_t bBase = (uint32_t)(((wn * 8 + (lane & 7)) * WSTR
                                 + ((lane >> 3) & 1) * 8 + ((lane >> 4) & 1) * 1024) * 2);

    int bb = tid >> 3, jl = tid & 7, j = blockIdx.x * 8 + jl;
    int bb2 = (tid + 256) >> 3;

    float c_reg[2];
    c_reg[0] = g_c0s[(LAYER * B_ + bb) * H_ + j];
    c_reg[1] = g_c0s[(LAYER * B_ + bb2) * H_ + j];

    float4 gp[2]; int rst[2];
    gp[0] = *(const float4*)&Gpre[(size_t)bb * G_ + n0 + 4 * jl];
    gp[1] = *(const float4*)&Gpre[(size_t)bb2 * G_ + n0 + 4 * jl];
    rst[0] = reset[bb];
    rst[1] = reset[bb2];
    __syncthreads();

    for (int t = 0; t < T_; t++) {
        const f16* Asrc = (LAYER == 0) ? (g_X1p + (size_t)t * B_ * H_) : g_h1p[t & 1];
        f16* Adst = (LAYER == 0) ? (g_X1p + (size_t)(t + 1) * B_ * H_) : g_h1p[(t + 1) & 1];

        float acc[2][4];
#pragma unroll
        for (int a = 0; a < 2; a++)
#pragma unroll
            for (int c = 0; c < 4; c++) acc[a][c] = 0.f;

        auto issue = [&](int c) {
            int k0 = c * 128, st = c & 3;
#pragma unroll
            for (int v = 0; v < 4; v++) {       // 64 rows x 16 segs (128 cols)
                int idx = tid + v * 256;
                int r = idx >> 4, s = idx & 15;
                cp_async16(&sA[st * 64 * ASTR + r * ASTR + s * 8], &Asrc[(size_t)r * H_ + k0 + s * 8]);
            }
            cp_commit();
        };

        issue(0); issue(1); issue(2);
        for (int c = 0; c < 8; c++) {
            if (c + 2 < 8) cp_wait<2>();
            else if (c + 1 < 8) cp_wait<1>();
            else cp_wait<0>();
            __syncthreads();
            if (c + 3 < 8) issue(c + 3);
            uint32_t stA = sA_u + (uint32_t)((c & 3) * 64 * ASTR * 2);
            uint32_t wOff = (uint32_t)(c * 128 * 2);   // k0 * 2 bytes
#pragma unroll
            for (int kk = 0; kk < 8; kk++) {
                uint32_t kbb = (uint32_t)(kk * 32);
                uint32_t Aa[2][4], Bq[4];
#pragma unroll
                for (int mt = 0; mt < 2; mt++)
                    ldsm4(Aa[mt][0], Aa[mt][1], Aa[mt][2], Aa[mt][3], stA + aBase[mt] + kbb);
                ldsm4(Bq[0], Bq[1], Bq[2], Bq[3], sW_u + bBase + wOff + kbb);
#pragma unroll
                for (int mt = 0; mt < 2; mt++) {
                    mma16816(acc[mt], Aa[mt][0], Aa[mt][1], Aa[mt][2], Aa[mt][3], Bq[0], Bq[1]);
                    mma16816(acc[mt], Aa[mt][0], Aa[mt][1], Aa[mt][2], Aa[mt][3], Bq[2], Bq[3]);
                }
            }
        }

        __syncthreads();
#pragma unroll
        for (int mt = 0; mt < 2; mt++) {
            int r0 = wm * 32 + mt * 16 + g;
            int c0 = wn * 8 + 2 * t4;
            zs[r0 * 36 + c0]     = acc[mt][0];
            zs[r0 * 36 + c0 + 1] = acc[mt][1];
            zs[(r0 + 8) * 36 + c0]     = acc[mt][2];
            zs[(r0 + 8) * 36 + c0 + 1] = acc[mt][3];
        }
        __syncthreads();

        float hn_s[2], cn_s[2];
#pragma unroll
        for (int it = 0; it < 2; it++) {
            int b = it ? bb2 : bb;
            float keep = 1.0f - (float)rst[it];
            float zi = gp[it].x + keep * zs[b * 36 + 4 * jl + 0];
            float zf = gp[it].y + keep * zs[b * 36 + 4 * jl + 1];
            float zg = gp[it].z + keep * zs[b * 36 + 4 * jl + 2];
            float zo = gp[it].w + keep * zs[b * 36 + 4 * jl + 3];
            float cn = sigmoidf_(zf) * keep * c_reg[it] + sigmoidf_(zi) * tanhf(zg);
            float hn = sigmoidf_(zo) * tanhf(cn);
            c_reg[it] = cn; cn_s[it] = cn; hn_s[it] = hn;
            Adst[b * H_ + j] = __float2half_rn(hn);
        }

        // split-phase two-level grid barrier: arrive
        __syncthreads();
        if (tid == 0) {
            __threadfence();
            unsigned grp = (unsigned)blockIdx.x >> 4;
            if (atomicAdd(&g_bar_grp[grp], 1u) == 15u) {
                g_bar_grp[grp] = 0u;
                if (atomicAdd(&g_bar_root, 1u) == 7u) {
                    g_bar_root = 0u;
                    __threadfence();
                    g_bar_gen = gen0 + t + 1;
                }
            }
        }

        // overlap: output stores + next-step prefetch
#pragma unroll
        for (int it = 0; it < 2; it++) {
            int b = it ? bb2 : bb;
            if (LAYER == 1)
                out[(size_t)t * B_ * H_ + b * H_ + j] = hn_s[it];
            if (t == T_ - 1) {
                out[OUTS_ + (b * 2 + LAYER) * H_ + j] = hn_s[it];
                out[OUTS_ + 2 * B_ * H_ + (b * 2 + LAYER) * H_ + j] = cn_s[it];
            }
        }
        if (t + 1 < T_) {
            gp[0] = *(const float4*)&Gpre[((size_t)(t + 1) * B_ + bb) * G_ + n0 + 4 * jl];
            gp[1] = *(const float4*)&Gpre[((size_t)(t + 1) * B_ + bb2) * G_ + n0 + 4 * jl];
            rst[0] = reset[(t + 1) * B_ + bb];
            rst[1] = reset[(t + 1) * B_ + bb2];
        }

        if (tid == 0) {
            while (ld_acq(&g_bar_gen) < gen0 + t + 1) { }
        }
        __syncthreads();
    }
}

__global__ __launch_bounds__(256, 1) void layer_kernel0(const int* __restrict__ reset, float* __restrict__ out)
{ layer_body<0>(reset, out); }
__global__ __launch_bounds__(256, 1) void layer_kernel1(const int* __restrict__ reset, float* __restrict__ out)
{ layer_body<1>(reset, out); }

// ---------------- launch ----------------
extern "C" void kernel_launch(void* const* d_in, const int* in_sizes, int n_in,
                              void* d_out, int out_size)
{
    (void)in_sizes; (void)n_in; (void)out_size;
    const float* input = (const float*)d_in[0];
    const int*   reset = (const int*)d_in[1];
    const float* h0    = (const float*)d_in[2];
    const float* c0    = (const float*)d_in[3];
    const float* Wi0   = (const float*)d_in[4];
    const float* Wh0   = (const float*)d_in[5];
    const float* bi0   = (const float*)d_in[6];
    const float* bh0   = (const float*)d_in[7];
    const float* Wi1   = (const float*)d_in[8];
    const float* Wh1   = (const float*)d_in[9];
    const float* bi1   = (const float*)d_in[10];
    const float* bh1   = (const float*)d_in[11];
    float* out = (float*)d_out;

    const int GEMM_SMEM  = 3 * 128 * (GAS + GBS) * 2;                     // 159744 B
    const int LAYER_SMEM = (32 * WSTR + 4 * 64 * ASTR) * 2 + 64 * 36 * 4; // 210432 B
    cudaFuncSetAttribute(gemm_kernel,   cudaFuncAttributeMaxDynamicSharedMemorySize, GEMM_SMEM);
    cudaFuncSetAttribute(layer_kernel0, cudaFuncAttributeMaxDynamicSharedMemorySize, LAYER_SMEM);
    cudaFuncSetAttribute(layer_kernel1, cudaFuncAttributeMaxDynamicSharedMemorySize, LAYER_SMEM);

    pack_w_kernel<<<1024, 256>>>(Wi0, 0, D_);
    pack_w_kernel<<<1024, 256>>>(Wh0, 1, H_);
    pack_w_kernel<<<1024, 256>>>(Wi1, 2, H_);
    pack_w_kernel<<<1024, 256>>>(Wh1, 3, H_);
    pack_x_kernel<<<1024, 256>>>(input);
    bias_kernel<<<16, 256>>>(bi0, bh0, bi1, bh1);
    init_state_kernel<<<512, 256>>>(h0, c0);

    gemm_kernel<<<dim3(32, 128), 256, GEMM_SMEM>>>(0);   // G0
    layer_kernel0<<<NB_, 256, LAYER_SMEM>>>(reset, out); // layer 0
    gemm_kernel<<<dim3(32, 128), 256, GEMM_SMEM>>>(1);   // G1
    layer_kernel1<<<NB_, 256, LAYER_SMEM>>>(reset, out); // layer 1
}

// round 7
// speedup vs baseline: 4.3338x; 1.2882x over previous
#include <cuda_runtime.h>
#include <cuda_fp16.h>
#include <cstdint>
#include <cstddef>

typedef __half f16;

#define T_ 256
#define B_ 64
#define D_ 512
#define H_ 1024
#define G_ 4096
#define TB_ (T_ * B_)
#define OUTS_ (TB_ * H_)
#define NB_ 128          // persistent grid size (layer kernels)

// ---------------- device scratch ----------------
__device__ f16   g_Xp  [(size_t)TB_ * D_];       // input fp16, stride 512
__device__ f16   g_Wi0p[(size_t)G_  * D_];       // single fp16 weights (gate-row permuted)
__device__ f16   g_Wh0p[(size_t)G_  * H_];
__device__ f16   g_Wi1p[(size_t)G_  * H_];
__device__ f16   g_Wh1p[(size_t)G_  * H_];
__device__ float g_b0[G_], g_b1[G_];
__device__ float g_G0[(size_t)TB_ * G_];
__device__ float g_G1[(size_t)TB_ * G_];
__device__ float g_c0s[2 * B_ * H_];
__device__ f16   g_X1p[(size_t)(T_ + 1) * B_ * H_];  // fp16, stride 1024
__device__ f16   g_h1p[2][B_ * H_];
__device__ unsigned g_bar_grp[8];    // zero-init
__device__ unsigned g_bar_root;      // zero-init
__device__ unsigned g_bar_gen;       // zero-init, monotonic

// ---------------- helpers ----------------
__device__ __forceinline__ void cp_async16(void* sdst, const void* gsrc) {
    uint32_t s = (uint32_t)__cvta_generic_to_shared(sdst);
    asm volatile("cp.async.cg.shared.global [%0], [%1], 16;\n" :: "r"(s), "l"(gsrc));
}
__device__ __forceinline__ void cp_commit() { asm volatile("cp.async.commit_group;\n"); }
template <int N> __device__ __forceinline__ void cp_wait() {
    asm volatile("cp.async.wait_group %0;\n" :: "n"(N));
}
__device__ __forceinline__ unsigned ld_acq(const unsigned* p) {
    unsigned v; asm volatile("ld.acquire.gpu.u32 %0, [%1];" : "=r"(v) : "l"(p)); return v;
}
__device__ __forceinline__ void mma16816(float* d,
    uint32_t a0, uint32_t a1, uint32_t a2, uint32_t a3, uint32_t b0, uint32_t b1)
{
    asm volatile(
        "mma.sync.aligned.m16n8k16.row.col.f32.f16.f16.f32 "
        "{%0,%1,%2,%3},{%4,%5,%6,%7},{%8,%9},{%0,%1,%2,%3};\n"
        : "+f"(d[0]), "+f"(d[1]), "+f"(d[2]), "+f"(d[3])
        : "r"(a0), "r"(a1), "r"(a2), "r"(a3), "r"(b0), "r"(b1));
}
__device__ __forceinline__ void ldsm4(uint32_t& a, uint32_t& b, uint32_t& c, uint32_t& d,
                                      uint32_t addr)
{
    asm volatile("ldmatrix.sync.aligned.m8n8.x4.shared.b16 {%0,%1,%2,%3}, [%4];"
        : "=r"(a), "=r"(b), "=r"(c), "=r"(d) : "r"(addr));
}
__device__ __forceinline__ float sigmoidf_(float z) { return 1.f / (1.f + __expf(-z)); }

// ---------------- packing ----------------
// weights: single fp16, gate-row permuted, stride K
__global__ void pack_w_kernel(const float* __restrict__ src, int which, int K)
{
    f16* dst = (which == 0) ? g_Wi0p : (which == 1) ? g_Wh0p :
               (which == 2) ? g_Wi1p : g_Wh1p;
    int K4 = K >> 2;
    int total = G_ * K4;
    for (int id = blockIdx.x * blockDim.x + threadIdx.x; id < total;
         id += gridDim.x * blockDim.x) {
        int r = id / K4, k4 = (id - r * K4) * 4;
        int sr = (r & 3) * H_ + (r >> 2);
        float4 v = *(const float4*)&src[(size_t)sr * K + k4];
        __half2 a = {__float2half_rn(v.x), __float2half_rn(v.y)};
        __half2 b = {__float2half_rn(v.z), __float2half_rn(v.w)};
        *(uint2*)&dst[(size_t)r * K + k4] = make_uint2(*(uint32_t*)&a, *(uint32_t*)&b);
    }
}

// input: single fp16, stride 512
__global__ void pack_x_kernel(const float* __restrict__ src)
{
    int total = TB_ * (D_ >> 2);
    for (int id = blockIdx.x * blockDim.x + threadIdx.x; id < total;
         id += gridDim.x * blockDim.x) {
        int r = id / (D_ >> 2), k4 = (id - r * (D_ >> 2)) * 4;
        float4 v = *(const float4*)&src[(size_t)r * D_ + k4];
        __half2 a = {__float2half_rn(v.x), __float2half_rn(v.y)};
        __half2 b = {__float2half_rn(v.z), __float2half_rn(v.w)};
        *(uint2*)&g_Xp[(size_t)r * D_ + k4] = make_uint2(*(uint32_t*)&a, *(uint32_t*)&b);
    }
}

__global__ void bias_kernel(const float* __restrict__ bi0, const float* __restrict__ bh0,
                            const float* __restrict__ bi1, const float* __restrict__ bh1)
{
    int r = blockIdx.x * blockDim.x + threadIdx.x;
    if (r < G_) {
        int sr = (r & 3) * H_ + (r >> 2);
        g_b0[r] = bi0[sr] + bh0[sr];
        g_b1[r] = bi1[sr] + bh1[sr];
    }
}

__global__ void init_state_kernel(const float* __restrict__ h0, const float* __restrict__ c0)
{
    int id = blockIdx.x * blockDim.x + threadIdx.x;
    if (id < 2 * B_ * H_) {
        int l = id / (B_ * H_);
        int b = (id / H_) % B_;
        int j = id % H_;
        float hv = h0[(b * 2 + l) * H_ + j];
        g_c0s[id] = c0[(b * 2 + l) * H_ + j];
        f16 hh = __float2half_rn(hv);
        if (l == 0) g_X1p[b * H_ + j] = hh;        // slot 0
        else        g_h1p[0][b * H_ + j] = hh;
    }
}

// ---------------- big GEMM: out = A @ B^T + bias (fp16 single) ----------------
// CTA tile 128x128, 256 threads (8 warps 2(M) x 4(N), warp tile 64x32), K-chunk 64,
// 3-stage cp.async ring.
#define GAS 72     // stage row stride (64 cols + 8 pad)
__global__ __launch_bounds__(256) void gemm_kernel(int sel)
{
    extern __shared__ f16 sm[];
    const int AS = 128 * GAS;
    f16* sA = sm;              // 3 stages
    f16* sB = sm + 3 * AS;     // 3 stages
    uint32_t sA_u = (uint32_t)__cvta_generic_to_shared(sA);
    uint32_t sB_u = (uint32_t)__cvta_generic_to_shared(sB);

    const f16 *A, *B; const float* bias; float* outp; int K;
    if (sel == 0) { A = g_Xp;  B = g_Wi0p; bias = g_b0; outp = g_G0; K = 512; }
    else { A = g_X1p + (size_t)B_ * H_; B = g_Wi1p; bias = g_b1; outp = g_G1; K = 1024; }

    int tid = threadIdx.x, w = tid >> 5, lane = tid & 31, g = lane >> 2, t4 = lane & 3;
    int wm = w & 1, wn = w >> 1;
    int m0 = blockIdx.y * 128, n0 = blockIdx.x * 128;
    int NC = K / 64;

    // ldmatrix per-lane bases (byte offsets within a stage)
    int lr = lane & 15;
    int lcA = (lane >> 4) * 8;
    uint32_t aBase[4], bBase[2];
#pragma unroll
    for (int mt = 0; mt < 4; mt++)
        aBase[mt] = (uint32_t)(((wm * 64 + mt * 16 + lr) * GAS + lcA) * 2);
#pragma unroll
    for (int p = 0; p < 2; p++)
        bBase[p] = (uint32_t)(((wn * 32 + p * 16 + (lane & 7) + ((lane >> 4) & 1) * 8) * GAS
                               + ((lane >> 3) & 1) * 8) * 2);

    float acc[4][4][4];
#pragma unroll
    for (int a = 0; a < 4; a++)
#pragma unroll
        for (int b = 0; b < 4; b++)
#pragma unroll
            for (int c = 0; c < 4; c++) acc[a][b][c] = 0.f;

    auto issue = [&](int c) {
        int k0 = c * 64;
        int st = c % 3;
#pragma unroll
        for (int v = 0; v < 4; v++) {           // A: 128 rows x 8 segs
            int idx = tid + v * 256;
            int r = idx >> 3, s = idx & 7;
            cp_async16(&sA[st * AS + r * GAS + s * 8], &A[(size_t)(m0 + r) * K + k0 + s * 8]);
        }
#pragma unroll
        for (int v = 0; v < 4; v++) {           // B: 128 rows x 8 segs
            int idx = tid + v * 256;
            int r = idx >> 3, s = idx & 7;
            cp_async16(&sB[st * AS + r * GAS + s * 8], &B[(size_t)(n0 + r) * K + k0 + s * 8]);
        }
        cp_commit();
    };

    issue(0); issue(1);
    for (int c = 0; c < NC; c++) {
        if (c + 1 < NC) cp_wait<1>(); else cp_wait<0>();
        __syncthreads();
        if (c + 2 < NC) issue(c + 2);
        uint32_t stA = sA_u + (uint32_t)((c % 3) * AS * 2);
        uint32_t stB = sB_u + (uint32_t)((c % 3) * AS * 2);
#pragma unroll
        for (int kk = 0; kk < 4; kk++) {
            uint32_t kbb = (uint32_t)(kk * 32);   // 16 elems * 2B
            uint32_t Aa[4][4], Bh[4][2];
#pragma unroll
            for (int mt = 0; mt < 4; mt++)
                ldsm4(Aa[mt][0], Aa[mt][1], Aa[mt][2], Aa[mt][3], stA + aBase[mt] + kbb);
#pragma unroll
            for (int p = 0; p < 2; p++)
                ldsm4(Bh[2 * p][0], Bh[2 * p][1], Bh[2 * p + 1][0], Bh[2 * p + 1][1],
                      stB + bBase[p] + kbb);
#pragma unroll
            for (int mt = 0; mt < 4; mt++)
#pragma unroll
                for (int nt = 0; nt < 4; nt++)
                    mma16816(acc[mt][nt], Aa[mt][0], Aa[mt][1], Aa[mt][2], Aa[mt][3], Bh[nt][0], Bh[nt][1]);
        }
    }

#pragma unroll
    for (int mt = 0; mt < 4; mt++)
#pragma unroll
        for (int nt = 0; nt < 4; nt++) {
            int row = m0 + wm * 64 + mt * 16 + g;
            int col = n0 + wn * 32 + nt * 8 + 2 * t4;
            float ba = bias[col], bb = bias[col + 1];
            *(float2*)&outp[(size_t)row * G_ + col] =
                make_float2(acc[mt][nt][0] + ba, acc[mt][nt][1] + bb);
            *(float2*)&outp[(size_t)(row + 8) * G_ + col] =
                make_float2(acc[mt][nt][2] + ba, acc[mt][nt][3] + bb);
        }
}

// ---------------- persistent layer kernel (fp16 single) ----------------
// A fp16 (stride 1024), W slice (32 x 1024 fp16 = 64KB) in SMEM.
// Chunk 128 cols, 8 chunks, 4-stage ring. One W-ldsm4 serves two k-steps.
#define WSTR 1032   // 1024 + 8 pad
#define ASTR 136    // 128 cols + 8 pad

template <int LAYER>
__device__ __forceinline__ void layer_body(const int* __restrict__ reset, float* __restrict__ out)
{
    extern __shared__ f16 smem[];
    f16* sW = smem;                             // 32 x WSTR
    f16* sA = smem + 32 * WSTR;                 // 4 x 64 x ASTR
    float* zs = (float*)(sA + 4 * 64 * ASTR);   // 64 x 36
    uint32_t sW_u = (uint32_t)__cvta_generic_to_shared(sW);
    uint32_t sA_u = (uint32_t)__cvta_generic_to_shared(sA);

    int tid = threadIdx.x, w = tid >> 5, lane = tid & 31, g = lane >> 2, t4 = lane & 3;
    int wm = w & 1, wn = w >> 1;
    int n0 = blockIdx.x * 32;
    unsigned gen0 = ld_acq(&g_bar_gen);

    const f16* Wsrc = (LAYER == 0 ? g_Wh0p : g_Wh1p) + (size_t)n0 * H_;
    for (int i = tid; i < 32 * 128; i += 256) {
        int r = i >> 7, s = i & 127;
        *(uint4*)&sW[r * WSTR + s * 8] = *(const uint4*)&Wsrc[(size_t)r * H_ + s * 8];
    }

    const float* Gpre = (LAYER == 0) ? g_G0 : g_G1;

    // ldmatrix per-lane bases
    int lr = lane & 15;
    int lcA = (lane >> 4) * 8;
    uint32_t aBase[2];
    aBase[0] = (uint32_t)(((wm * 32 + 0 + lr) * ASTR + lcA) * 2);
    aBase[1] = (uint32_t)(((wm * 32 + 16 + lr) * ASTR + lcA) * 2);
    // W x4 loads TWO k-steps: m0,m1 = kk (k0,k1-half), m2,m3 = kk+1
    uint32_t bBase = (uint32_t)(((wn * 8 + (lane & 7)) * WSTR
                                 + ((lane >> 3) & 1) * 8 + ((lane >> 4) & 1) * 16) * 2);

    int bb = tid >> 3, jl = tid & 7, j = blockIdx.x * 8 + jl;
    int bb2 = (tid + 256) >> 3;

    float c_reg[2];
    c_reg[0] = g_c0s[(LAYER * B_ + bb) * H_ + j];
    c_reg[1] = g_c0s[(LAYER * B_ + bb2) * H_ + j];

    float4 gp[2]; int rst[2];
    gp[0] = *(const float4*)&Gpre[(size_t)bb * G_ + n0 + 4 * jl];
    gp[1] = *(const float4*)&Gpre[(size_t)bb2 * G_ + n0 + 4 * jl];
    rst[0] = reset[bb];
    rst[1] = reset[bb2];
    __syncthreads();

    for (int t = 0; t < T_; t++) {
        const f16* Asrc = (LAYER == 0) ? (g_X1p + (size_t)t * B_ * H_) : g_h1p[t & 1];
        f16* Adst = (LAYER == 0) ? (g_X1p + (size_t)(t + 1) * B_ * H_) : g_h1p[(t + 1) & 1];

        float acc[2][4];
#pragma unroll
        for (int a = 0; a < 2; a++)
#pragma unroll
            for (int c = 0; c < 4; c++) acc[a][c] = 0.f;

        auto issue = [&](int c) {
            int k0 = c * 128, st = c & 3;
#pragma unroll
            for (int v = 0; v < 4; v++) {       // 64 rows x 16 segs (128 cols)
                int idx = tid + v * 256;
                int r = idx >> 4, s = idx & 15;
                cp_async16(&sA[st * 64 * ASTR + r * ASTR + s * 8], &Asrc[(size_t)r * H_ + k0 + s * 8]);
            }
            cp_commit();
        };

        issue(0); issue(1); issue(2);
        for (int c = 0; c < 8; c++) {
            if (c + 2 < 8) cp_wait<2>();
            else if (c + 1 < 8) cp_wait<1>();
            else cp_wait<0>();
            __syncthreads();
            if (c + 3 < 8) issue(c + 3);
            uint32_t stA = sA_u + (uint32_t)((c & 3) * 64 * ASTR * 2);
            uint32_t wOff = (uint32_t)(c * 128 * 2);   // k0 bytes
#pragma unroll
            for (int kp = 0; kp < 4; kp++) {           // pairs of k-steps
                uint32_t Bq[4];
                ldsm4(Bq[0], Bq[1], Bq[2], Bq[3], sW_u + bBase + wOff + (uint32_t)(kp * 64));
#pragma unroll
                for (int h = 0; h < 2; h++) {
                    uint32_t kbb = (uint32_t)(kp * 64 + h * 32);
                    uint32_t Aa[2][4];
#pragma unroll
                    for (int mt = 0; mt < 2; mt++)
                        ldsm4(Aa[mt][0], Aa[mt][1], Aa[mt][2], Aa[mt][3], stA + aBase[mt] + kbb);
#pragma unroll
                    for (int mt = 0; mt < 2; mt++)
                        mma16816(acc[mt], Aa[mt][0], Aa[mt][1], Aa[mt][2], Aa[mt][3],
                                 Bq[h * 2], Bq[h * 2 + 1]);
                }
            }
        }

        __syncthreads();
#pragma unroll
        for (int mt = 0; mt < 2; mt++) {
            int r0 = wm * 32 + mt * 16 + g;
            int c0 = wn * 8 + 2 * t4;
            zs[r0 * 36 + c0]     = acc[mt][0];
            zs[r0 * 36 + c0 + 1] = acc[mt][1];
            zs[(r0 + 8) * 36 + c0]     = acc[mt][2];
            zs[(r0 + 8) * 36 + c0 + 1] = acc[mt][3];
        }
        __syncthreads();

        float hn_s[2], cn_s[2];
#pragma unroll
        for (int it = 0; it < 2; it++) {
            int b = it ? bb2 : bb;
            float keep = 1.0f - (float)rst[it];
            float zi = gp[it].x + keep * zs[b * 36 + 4 * jl + 0];
            float zf = gp[it].y + keep * zs[b * 36 + 4 * jl + 1];
            float zg = gp[it].z + keep * zs[b * 36 + 4 * jl + 2];
            float zo = gp[it].w + keep * zs[b * 36 + 4 * jl + 3];
            float cn = sigmoidf_(zf) * keep * c_reg[it] + sigmoidf_(zi) * tanhf(zg);
            float hn = sigmoidf_(zo) * tanhf(cn);
            c_reg[it] = cn; cn_s[it] = cn; hn_s[it] = hn;
            Adst[b * H_ + j] = __float2half_rn(hn);
        }

        // split-phase two-level grid barrier: arrive
        __syncthreads();
        if (tid == 0) {
            __threadfence();
            unsigned grp = (unsigned)blockIdx.x >> 4;
            if (atomicAdd(&g_bar_grp[grp], 1u) == 15u) {
                g_bar_grp[grp] = 0u;
                if (atomicAdd(&g_bar_root, 1u) == 7u) {
                    g_bar_root = 0u;
                    __threadfence();
                    g_bar_gen = gen0 + t + 1;
                }
            }
        }

        // overlap: output stores + next-step prefetch
#pragma unroll
        for (int it = 0; it < 2; it++) {
            int b = it ? bb2 : bb;
            if (LAYER == 1)
                out[(size_t)t * B_ * H_ + b * H_ + j] = hn_s[it];
            if (t == T_ - 1) {
                out[OUTS_ + (b * 2 + LAYER) * H_ + j] = hn_s[it];
                out[OUTS_ + 2 * B_ * H_ + (b * 2 + LAYER) * H_ + j] = cn_s[it];
            }
        }
        if (t + 1 < T_) {
            gp[0] = *(const float4*)&Gpre[((size_t)(t + 1) * B_ + bb) * G_ + n0 + 4 * jl];
            gp[1] = *(const float4*)&Gpre[((size_t)(t + 1) * B_ + bb2) * G_ + n0 + 4 * jl];
            rst[0] = reset[(t + 1) * B_ + bb];
            rst[1] = reset[(t + 1) * B_ + bb2];
        }

        if (tid == 0) {
            while (ld_acq(&g_bar_gen) < gen0 + t + 1) { }
        }
        __syncthreads();
    }
}

__global__ __launch_bounds__(256, 1) void layer_kernel0(const int* __restrict__ reset, float* __restrict__ out)
{ layer_body<0>(reset, out); }
__global__ __launch_bounds__(256, 1) void layer_kernel1(const int* __restrict__ reset, float* __restrict__ out)
{ layer_body<1>(reset, out); }

// ---------------- launch ----------------
extern "C" void kernel_launch(void* const* d_in, const int* in_sizes, int n_in,
                              void* d_out, int out_size)
{
    (void)in_sizes; (void)n_in; (void)out_size;
    const float* input = (const float*)d_in[0];
    const int*   reset = (const int*)d_in[1];
    const float* h0    = (const float*)d_in[2];
    const float* c0    = (const float*)d_in[3];
    const float* Wi0   = (const float*)d_in[4];
    const float* Wh0   = (const float*)d_in[5];
    const float* bi0   = (const float*)d_in[6];
    const float* bh0   = (const float*)d_in[7];
    const float* Wi1   = (const float*)d_in[8];
    const float* Wh1   = (const float*)d_in[9];
    const float* bi1   = (const float*)d_in[10];
    const float* bh1   = (const float*)d_in[11];
    float* out = (float*)d_out;

    const int GEMM_SMEM  = 6 * 128 * GAS * 2;                             // 110592 B
    const int LAYER_SMEM = (32 * WSTR + 4 * 64 * ASTR) * 2 + 64 * 36 * 4; // 144896 B
    cudaFuncSetAttribute(gemm_kernel,   cudaFuncAttributeMaxDynamicSharedMemorySize, GEMM_SMEM);
    cudaFuncSetAttribute(layer_kernel0, cudaFuncAttributeMaxDynamicSharedMemorySize, LAYER_SMEM);
    cudaFuncSetAttribute(layer_kernel1, cudaFuncAttributeMaxDynamicSharedMemorySize, LAYER_SMEM);

    pack_w_kernel<<<1024, 256>>>(Wi0, 0, D_);
    pack_w_kernel<<<1024, 256>>>(Wh0, 1, H_);
    pack_w_kernel<<<1024, 256>>>(Wi1, 2, H_);
    pack_w_kernel<<<1024, 256>>>(Wh1, 3, H_);
    pack_x_kernel<<<1024, 256>>>(input);
    bias_kernel<<<16, 256>>>(bi0, bh0, bi1, bh1);
    init_state_kernel<<<512, 256>>>(h0, c0);

    gemm_kernel<<<dim3(32, 128), 256, GEMM_SMEM>>>(0);   // G0
    layer_kernel0<<<NB_, 256, LAYER_SMEM>>>(reset, out); // layer 0
    gemm_kernel<<<dim3(32, 128), 256, GEMM_SMEM>>>(1);   // G1
    layer_kernel1<<<NB_, 256, LAYER_SMEM>>>(reset, out); // layer 1
}

// round 9
// speedup vs baseline: 4.6946x; 1.0832x over previous
#include <cuda_runtime.h>
#include <cuda_fp16.h>
#include <cstdint>
#include <cstddef>

typedef __half f16;

#define T_ 256
#define B_ 64
#define D_ 512
#define H_ 1024
#define G_ 4096
#define TB_ (T_ * B_)
#define OUTS_ (TB_ * H_)
#define NB_ 128          // persistent grid size (layer kernels)

// ---------------- device scratch ----------------
__device__ f16   g_Xp  [(size_t)TB_ * D_];       // input fp16, stride 512
__device__ f16   g_Wi0p[(size_t)G_  * D_];       // single fp16 weights (gate-row permuted)
__device__ f16   g_Wh0p[(size_t)G_  * H_];
__device__ f16   g_Wi1p[(size_t)G_  * H_];
__device__ f16   g_Wh1p[(size_t)G_  * H_];
__device__ float g_b0[G_], g_b1[G_];
__device__ float g_G0[(size_t)TB_ * G_];
__device__ float g_G1[(size_t)TB_ * G_];
__device__ float g_c0s[2 * B_ * H_];
__device__ f16   g_X1p[(size_t)(T_ + 1) * B_ * H_];  // fp16, stride 1024
__device__ f16   g_h1p[2][B_ * H_];
__device__ unsigned g_bar_grp[8];    // zero-init
__device__ unsigned g_bar_root;      // zero-init
__device__ unsigned g_bar_gen;       // zero-init, monotonic

// ---------------- helpers ----------------
__device__ __forceinline__ void cp_async16(void* sdst, const void* gsrc) {
    uint32_t s = (uint32_t)__cvta_generic_to_shared(sdst);
    asm volatile("cp.async.cg.shared.global [%0], [%1], 16;\n" :: "r"(s), "l"(gsrc));
}
__device__ __forceinline__ void cp_commit() { asm volatile("cp.async.commit_group;\n"); }
template <int N> __device__ __forceinline__ void cp_wait() {
    asm volatile("cp.async.wait_group %0;\n" :: "n"(N));
}
__device__ __forceinline__ unsigned ld_acq(const unsigned* p) {
    unsigned v; asm volatile("ld.acquire.gpu.u32 %0, [%1];" : "=r"(v) : "l"(p)); return v;
}
__device__ __forceinline__ void mma16816(float* d,
    uint32_t a0, uint32_t a1, uint32_t a2, uint32_t a3, uint32_t b0, uint32_t b1)
{
    asm volatile(
        "mma.sync.aligned.m16n8k16.row.col.f32.f16.f16.f32 "
        "{%0,%1,%2,%3},{%4,%5,%6,%7},{%8,%9},{%0,%1,%2,%3};\n"
        : "+f"(d[0]), "+f"(d[1]), "+f"(d[2]), "+f"(d[3])
        : "r"(a0), "r"(a1), "r"(a2), "r"(a3), "r"(b0), "r"(b1));
}
__device__ __forceinline__ void ldsm4(uint32_t& a, uint32_t& b, uint32_t& c, uint32_t& d,
                                      uint32_t addr)
{
    asm volatile("ldmatrix.sync.aligned.m8n8.x4.shared.b16 {%0,%1,%2,%3}, [%4];"
        : "=r"(a), "=r"(b), "=r"(c), "=r"(d) : "r"(addr));
}
__device__ __forceinline__ float sigmoidf_(float z) { return 1.f / (1.f + __expf(-z)); }

// ---------------- packing ----------------
__global__ void pack_w_kernel(const float* __restrict__ src, int which, int K)
{
    f16* dst = (which == 0) ? g_Wi0p : (which == 1) ? g_Wh0p :
               (which == 2) ? g_Wi1p : g_Wh1p;
    int K4 = K >> 2;
    int total = G_ * K4;
    for (int id = blockIdx.x * blockDim.x + threadIdx.x; id < total;
         id += gridDim.x * blockDim.x) {
        int r = id / K4, k4 = (id - r * K4) * 4;
        int sr = (r & 3) * H_ + (r >> 2);
        float4 v = *(const float4*)&src[(size_t)sr * K + k4];
        __half2 a = {__float2half_rn(v.x), __float2half_rn(v.y)};
        __half2 b = {__float2half_rn(v.z), __float2half_rn(v.w)};
        *(uint2*)&dst[(size_t)r * K + k4] = make_uint2(*(uint32_t*)&a, *(uint32_t*)&b);
    }
}

__global__ void pack_x_kernel(const float* __restrict__ src)
{
    int total = TB_ * (D_ >> 2);
    for (int id = blockIdx.x * blockDim.x + threadIdx.x; id < total;
         id += gridDim.x * blockDim.x) {
        int r = id / (D_ >> 2), k4 = (id - r * (D_ >> 2)) * 4;
        float4 v = *(const float4*)&src[(size_t)r * D_ + k4];
        __half2 a = {__float2half_rn(v.x), __float2half_rn(v.y)};
        __half2 b = {__float2half_rn(v.z), __float2half_rn(v.w)};
        *(uint2*)&g_Xp[(size_t)r * D_ + k4] = make_uint2(*(uint32_t*)&a, *(uint32_t*)&b);
    }
}

__global__ void bias_kernel(const float* __restrict__ bi0, const float* __restrict__ bh0,
                            const float* __restrict__ bi1, const float* __restrict__ bh1)
{
    int r = blockIdx.x * blockDim.x + threadIdx.x;
    if (r < G_) {
        int sr = (r & 3) * H_ + (r >> 2);
        g_b0[r] = bi0[sr] + bh0[sr];
        g_b1[r] = bi1[sr] + bh1[sr];
    }
}

__global__ void init_state_kernel(const float* __restrict__ h0, const float* __restrict__ c0)
{
    int id = blockIdx.x * blockDim.x + threadIdx.x;
    if (id < 2 * B_ * H_) {
        int l = id / (B_ * H_);
        int b = (id / H_) % B_;
        int j = id % H_;
        float hv = h0[(b * 2 + l) * H_ + j];
        g_c0s[id] = c0[(b * 2 + l) * H_ + j];
        f16 hh = __float2half_rn(hv);
        if (l == 0) g_X1p[b * H_ + j] = hh;        // slot 0
        else        g_h1p[0][b * H_ + j] = hh;
    }
}

// ---------------- big GEMM: out = A @ B^T + bias (fp16 single) ----------------
// CTA tile 128x128, 256 threads (8 warps 2(M) x 4(N), warp tile 64x32), K-chunk 64,
// 3-stage cp.async ring (distance-2 issue: safe).
#define GAS 72     // stage row stride (64 cols + 8 pad)
__global__ __launch_bounds__(256) void gemm_kernel(int sel)
{
    extern __shared__ f16 sm[];
    const int AS = 128 * GAS;
    f16* sA = sm;              // 3 stages
    f16* sB = sm + 3 * AS;     // 3 stages
    uint32_t sA_u = (uint32_t)__cvta_generic_to_shared(sA);
    uint32_t sB_u = (uint32_t)__cvta_generic_to_shared(sB);

    const f16 *A, *B; const float* bias; float* outp; int K;
    if (sel == 0) { A = g_Xp;  B = g_Wi0p; bias = g_b0; outp = g_G0; K = 512; }
    else { A = g_X1p + (size_t)B_ * H_; B = g_Wi1p; bias = g_b1; outp = g_G1; K = 1024; }

    int tid = threadIdx.x, w = tid >> 5, lane = tid & 31, g = lane >> 2, t4 = lane & 3;
    int wm = w & 1, wn = w >> 1;
    int m0 = blockIdx.y * 128, n0 = blockIdx.x * 128;
    int NC = K / 64;

    int lr = lane & 15;
    int lcA = (lane >> 4) * 8;
    uint32_t aBase[4], bBase[2];
#pragma unroll
    for (int mt = 0; mt < 4; mt++)
        aBase[mt] = (uint32_t)(((wm * 64 + mt * 16 + lr) * GAS + lcA) * 2);
#pragma unroll
    for (int p = 0; p < 2; p++)
        bBase[p] = (uint32_t)(((wn * 32 + p * 16 + (lane & 7) + ((lane >> 4) & 1) * 8) * GAS
                               + ((lane >> 3) & 1) * 8) * 2);

    float acc[4][4][4];
#pragma unroll
    for (int a = 0; a < 4; a++)
#pragma unroll
        for (int b = 0; b < 4; b++)
#pragma unroll
            for (int c = 0; c < 4; c++) acc[a][b][c] = 0.f;

    auto issue = [&](int c) {
        int k0 = c * 64;
        int st = c % 3;
#pragma unroll
        for (int v = 0; v < 4; v++) {
            int idx = tid + v * 256;
            int r = idx >> 3, s = idx & 7;
            cp_async16(&sA[st * AS + r * GAS + s * 8], &A[(size_t)(m0 + r) * K + k0 + s * 8]);
        }
#pragma unroll
        for (int v = 0; v < 4; v++) {
            int idx = tid + v * 256;
            int r = idx >> 3, s = idx & 7;
            cp_async16(&sB[st * AS + r * GAS + s * 8], &B[(size_t)(n0 + r) * K + k0 + s * 8]);
        }
        cp_commit();
    };

    issue(0); issue(1);
    for (int c = 0; c < NC; c++) {
        if (c + 1 < NC) cp_wait<1>(); else cp_wait<0>();
        __syncthreads();
        if (c + 2 < NC) issue(c + 2);
        uint32_t stA = sA_u + (uint32_t)((c % 3) * AS * 2);
        uint32_t stB = sB_u + (uint32_t)((c % 3) * AS * 2);
#pragma unroll
        for (int kk = 0; kk < 4; kk++) {
            uint32_t kbb = (uint32_t)(kk * 32);
            uint32_t Aa[4][4], Bh[4][2];
#pragma unroll
            for (int mt = 0; mt < 4; mt++)
                ldsm4(Aa[mt][0], Aa[mt][1], Aa[mt][2], Aa[mt][3], stA + aBase[mt] + kbb);
#pragma unroll
            for (int p = 0; p < 2; p++)
                ldsm4(Bh[2 * p][0], Bh[2 * p][1], Bh[2 * p + 1][0], Bh[2 * p + 1][1],
                      stB + bBase[p] + kbb);
#pragma unroll
            for (int mt = 0; mt < 4; mt++)
#pragma unroll
                for (int nt = 0; nt < 4; nt++)
                    mma16816(acc[mt][nt], Aa[mt][0], Aa[mt][1], Aa[mt][2], Aa[mt][3], Bh[nt][0], Bh[nt][1]);
        }
    }

#pragma unroll
    for (int mt = 0; mt < 4; mt++)
#pragma unroll
        for (int nt = 0; nt < 4; nt++) {
            int row = m0 + wm * 64 + mt * 16 + g;
            int col = n0 + wn * 32 + nt * 8 + 2 * t4;
            float ba = bias[col], bb = bias[col + 1];
            *(float2*)&outp[(size_t)row * G_ + col] =
                make_float2(acc[mt][nt][0] + ba, acc[mt][nt][1] + bb);
            *(float2*)&outp[(size_t)(row + 8) * G_ + col] =
                make_float2(acc[mt][nt][2] + ba, acc[mt][nt][3] + bb);
        }
}

// ---------------- persistent layer kernel (fp16, wm2 x wn2 x wk2) ----------------
// A fp16 (stride 1024), W slice (32 x 1024 fp16 = 64KB) in SMEM.
// Chunk 128 cols, 8 chunks, 4-stage ring (distance-3 issue: safe with 4 stages).
// Warp tile m32 x n16, K split by wk over interleaved k32 blocks.
// zs has 2 banks (one per wk), summed in the tail.
#define WSTR 1032   // 1024 + 8 pad
#define ASTR 136    // 128 cols + 8 pad
#define ASTG (64 * ASTR)

template <int LAYER>
__device__ __forceinline__ void layer_body(const int* __restrict__ reset, float* __restrict__ out)
{
    extern __shared__ f16 smem[];
    f16* sW = smem;                             // 32 x WSTR
    f16* sA = smem + 32 * WSTR;                 // 4 x ASTG
    float* zs = (float*)(sA + 4 * ASTG);        // 2 banks x 64 x 36
    uint32_t sW_u = (uint32_t)__cvta_generic_to_shared(sW);
    uint32_t sA_u = (uint32_t)__cvta_generic_to_shared(sA);

    int tid = threadIdx.x, w = tid >> 5, lane = tid & 31, g = lane >> 2, t4 = lane & 3;
    int wk = w & 1, wn = (w >> 1) & 1, wm = w >> 2;
    int n0 = blockIdx.x * 32;
    unsigned gen0 = ld_acq(&g_bar_gen);

    const f16* Wsrc = (LAYER == 0 ? g_Wh0p : g_Wh1p) + (size_t)n0 * H_;
    for (int i = tid; i < 32 * 128; i += 256) {
        int r = i >> 7, s = i & 127;
        *(uint4*)&sW[r * WSTR + s * 8] = *(const uint4*)&Wsrc[(size_t)r * H_ + s * 8];
    }

    const float* Gpre = (LAYER == 0) ? g_G0 : g_G1;

    // ldmatrix per-lane bases
    int lr = lane & 15;
    int lcA = (lane >> 4) * 8;
    uint32_t aBase[2];
    aBase[0] = (uint32_t)(((wm * 32 + 0 + lr) * ASTR + lcA) * 2);
    aBase[1] = (uint32_t)(((wm * 32 + 16 + lr) * ASTR + lcA) * 2);
    // B x4 loads n8 x k32 (tiles at k+0,8,16,24) for one n8 group
    uint32_t bBase[2];
#pragma unroll
    for (int nt = 0; nt < 2; nt++)
        bBase[nt] = (uint32_t)(((wn * 16 + nt * 8 + (lane & 7)) * WSTR
                                + ((lane >> 3) & 1) * 8 + ((lane >> 4) & 1) * 16) * 2);

    int bb = tid >> 3, jl = tid & 7, j = blockIdx.x * 8 + jl;
    int bb2 = (tid + 256) >> 3;

    float c_reg[2];
    c_reg[0] = g_c0s[(LAYER * B_ + bb) * H_ + j];
    c_reg[1] = g_c0s[(LAYER * B_ + bb2) * H_ + j];

    float4 gp[2]; int rst[2];
    gp[0] = *(const float4*)&Gpre[(size_t)bb * G_ + n0 + 4 * jl];
    gp[1] = *(const float4*)&Gpre[(size_t)bb2 * G_ + n0 + 4 * jl];
    rst[0] = reset[bb];
    rst[1] = reset[bb2];
    __syncthreads();

    for (int t = 0; t < T_; t++) {
        const f16* Asrc = (LAYER == 0) ? (g_X1p + (size_t)t * B_ * H_) : g_h1p[t & 1];
        f16* Adst = (LAYER == 0) ? (g_X1p + (size_t)(t + 1) * B_ * H_) : g_h1p[(t + 1) & 1];

        float acc[2][2][4];
#pragma unroll
        for (int a = 0; a < 2; a++)
#pragma unroll
            for (int b = 0; b < 2; b++)
#pragma unroll
                for (int c = 0; c < 4; c++) acc[a][b][c] = 0.f;

        auto issue = [&](int c) {
            int k0 = c * 128, st = c & 3;
#pragma unroll
            for (int v = 0; v < 4; v++) {       // 64 rows x 16 segs (128 cols)
                int idx = tid + v * 256;
                int r = idx >> 4, s = idx & 15;
                cp_async16(&sA[st * ASTG + r * ASTR + s * 8], &Asrc[(size_t)r * H_ + k0 + s * 8]);
            }
            cp_commit();
        };

        issue(0); issue(1); issue(2);
        for (int c = 0; c < 8; c++) {
            if (c + 2 < 8) cp_wait<2>();
            else if (c + 1 < 8) cp_wait<1>();
            else cp_wait<0>();
            __syncthreads();
            if (c + 3 < 8) issue(c + 3);
            uint32_t stA = sA_u + (uint32_t)((c & 3) * ASTG * 2);
            uint32_t wOffC = (uint32_t)(c * 128 * 2);
#pragma unroll
            for (int kpi = 0; kpi < 2; kpi++) {
                int kp = kpi * 2 + wk;                       // this warp's k32 block in chunk
                uint32_t kpb = (uint32_t)(kp * 64);          // byte offset of k32 block
                uint32_t Bq[2][4];
#pragma unroll
                for (int nt = 0; nt < 2; nt++)
                    ldsm4(Bq[nt][0], Bq[nt][1], Bq[nt][2], Bq[nt][3],
                          sW_u + bBase[nt] + wOffC + kpb);
#pragma unroll
                for (int h = 0; h < 2; h++) {
                    uint32_t kbb = kpb + (uint32_t)(h * 32);
                    uint32_t Aa[2][4];
#pragma unroll
                    for (int mt = 0; mt < 2; mt++)
                        ldsm4(Aa[mt][0], Aa[mt][1], Aa[mt][2], Aa[mt][3], stA + aBase[mt] + kbb);
#pragma unroll
                    for (int mt = 0; mt < 2; mt++)
#pragma unroll
                        for (int nt = 0; nt < 2; nt++)
                            mma16816(acc[mt][nt], Aa[mt][0], Aa[mt][1], Aa[mt][2], Aa[mt][3],
                                     Bq[nt][h * 2], Bq[nt][h * 2 + 1]);
                }
            }
        }

        // write partial sums to this wk's zs bank
        float* zb = zs + wk * (64 * 36);
#pragma unroll
        for (int mt = 0; mt < 2; mt++)
#pragma unroll
            for (int nt = 0; nt < 2; nt++) {
                int r0 = wm * 32 + mt * 16 + g;
                int c0 = wn * 16 + nt * 8 + 2 * t4;
                zb[r0 * 36 + c0]     = acc[mt][nt][0];
                zb[r0 * 36 + c0 + 1] = acc[mt][nt][1];
                zb[(r0 + 8) * 36 + c0]     = acc[mt][nt][2];
                zb[(r0 + 8) * 36 + c0 + 1] = acc[mt][nt][3];
            }
        __syncthreads();

        float hn_s[2], cn_s[2];
#pragma unroll
        for (int it = 0; it < 2; it++) {
            int b = it ? bb2 : bb;
            float keep = 1.0f - (float)rst[it];
            int zi_i = b * 36 + 4 * jl;
            float zi = gp[it].x + keep * (zs[zi_i + 0] + zs[64 * 36 + zi_i + 0]);
            float zf = gp[it].y + keep * (zs[zi_i + 1] + zs[64 * 36 + zi_i + 1]);
            float zg = gp[it].z + keep * (zs[zi_i + 2] + zs[64 * 36 + zi_i + 2]);
            float zo = gp[it].w + keep * (zs[zi_i + 3] + zs[64 * 36 + zi_i + 3]);
            float cn = sigmoidf_(zf) * keep * c_reg[it] + sigmoidf_(zi) * tanhf(zg);
            float hn = sigmoidf_(zo) * tanhf(cn);
            c_reg[it] = cn; cn_s[it] = cn; hn_s[it] = hn;
            Adst[b * H_ + j] = __float2half_rn(hn);
        }

        // split-phase two-level grid barrier: arrive
        __syncthreads();
        if (tid == 0) {
            __threadfence();
            unsigned grp = (unsigned)blockIdx.x >> 4;
            if (atomicAdd(&g_bar_grp[grp], 1u) == 15u) {
                g_bar_grp[grp] = 0u;
                if (atomicAdd(&g_bar_root, 1u) == 7u) {
                    g_bar_root = 0u;
                    __threadfence();
                    g_bar_gen = gen0 + t + 1;
                }
            }
        }

        // overlap: output stores + next-step prefetch
#pragma unroll
        for (int it = 0; it < 2; it++) {
            int b = it ? bb2 : bb;
            if (LAYER == 1)
                out[(size_t)t * B_ * H_ + b * H_ + j] = hn_s[it];
            if (t == T_ - 1) {
                out[OUTS_ + (b * 2 + LAYER) * H_ + j] = hn_s[it];
                out[OUTS_ + 2 * B_ * H_ + (b * 2 + LAYER) * H_ + j] = cn_s[it];
            }
        }
        if (t + 1 < T_) {
            gp[0] = *(const float4*)&Gpre[((size_t)(t + 1) * B_ + bb) * G_ + n0 + 4 * jl];
            gp[1] = *(const float4*)&Gpre[((size_t)(t + 1) * B_ + bb2) * G_ + n0 + 4 * jl];
            rst[0] = reset[(t + 1) * B_ + bb];
            rst[1] = reset[(t + 1) * B_ + bb2];
        }

        if (tid == 0) {
            while (ld_acq(&g_bar_gen) < gen0 + t + 1) { }
        }
        __syncthreads();
    }
}

__global__ __launch_bounds__(256, 1) void layer_kernel0(const int* __restrict__ reset, float* __restrict__ out)
{ layer_body<0>(reset, out); }
__global__ __launch_bounds__(256, 1) void layer_kernel1(const int* __restrict__ reset, float* __restrict__ out)
{ layer_body<1>(reset, out); }

// ---------------- launch ----------------
extern "C" void kernel_launch(void* const* d_in, const int* in_sizes, int n_in,
                              void* d_out, int out_size)
{
    (void)in_sizes; (void)n_in; (void)out_size;
    const float* input = (const float*)d_in[0];
    const int*   reset = (const int*)d_in[1];
    const float* h0    = (const float*)d_in[2];
    const float* c0    = (const float*)d_in[3];
    const float* Wi0   = (const float*)d_in[4];
    const float* Wh0   = (const float*)d_in[5];
    const float* bi0   = (const float*)d_in[6];
    const float* bh0   = (const float*)d_in[7];
    const float* Wi1   = (const float*)d_in[8];
    const float* Wh1   = (const float*)d_in[9];
    const float* bi1   = (const float*)d_in[10];
    const float* bh1   = (const float*)d_in[11];
    float* out = (float*)d_out;

    const int GEMM_SMEM  = 6 * 128 * GAS * 2;                             // 110592 B
    const int LAYER_SMEM = (32 * WSTR + 4 * ASTG) * 2 + 2 * 64 * 36 * 4;  // 154112 B
    cudaFuncSetAttribute(gemm_kernel,   cudaFuncAttributeMaxDynamicSharedMemorySize, GEMM_SMEM);
    cudaFuncSetAttribute(layer_kernel0, cudaFuncAttributeMaxDynamicSharedMemorySize, LAYER_SMEM);
    cudaFuncSetAttribute(layer_kernel1, cudaFuncAttributeMaxDynamicSharedMemorySize, LAYER_SMEM);

    pack_w_kernel<<<1024, 256>>>(Wi0, 0, D_);
    pack_w_kernel<<<1024, 256>>>(Wh0, 1, H_);
    pack_w_kernel<<<1024, 256>>>(Wi1, 2, H_);
    pack_w_kernel<<<1024, 256>>>(Wh1, 3, H_);
    pack_x_kernel<<<1024, 256>>>(input);
    bias_kernel<<<16, 256>>>(bi0, bh0, bi1, bh1);
    init_state_kernel<<<512, 256>>>(h0, c0);

    gemm_kernel<<<dim3(32, 128), 256, GEMM_SMEM>>>(0);   // G0
    layer_kernel0<<<NB_, 256, LAYER_SMEM>>>(reset, out); // layer 0
    gemm_kernel<<<dim3(32, 128), 256, GEMM_SMEM>>>(1);   // G1
    layer_kernel1<<<NB_, 256, LAYER_SMEM>>>(reset, out); // layer 1
}

// round 10
// speedup vs baseline: 5.8060x; 1.2367x over previous
#include <cuda_runtime.h>
#include <cuda_fp16.h>
#include <cstdint>
#include <cstddef>

typedef __half f16;

#define T_ 256
#define B_ 64
#define D_ 512
#define H_ 1024
#define G_ 4096
#define TB_ (T_ * B_)
#define OUTS_ (TB_ * H_)
#define NB_ 128          // persistent grid size

// ---------------- device scratch ----------------
__device__ f16   g_Xp  [(size_t)TB_ * D_];       // input fp16, stride 512
__device__ f16   g_Wi0p[(size_t)G_  * D_];       // fp16 weights (gate-row permuted)
__device__ f16   g_Wh0p[(size_t)G_  * H_];
__device__ f16   g_Wi1p[(size_t)G_  * H_];
__device__ f16   g_Wh1p[(size_t)G_  * H_];
__device__ float g_b0[G_], g_b1[G_];
__device__ float g_G0[(size_t)TB_ * G_];
__device__ float g_c0s[2 * B_ * H_];
__device__ f16   g_h0p[2][B_ * H_];              // h0 ping-pong
__device__ f16   g_h1p[2][B_ * H_];              // h1 ping-pong
__device__ unsigned g_bar_grp[8];    // zero-init
__device__ unsigned g_bar_root;      // zero-init
__device__ unsigned g_bar_gen;       // zero-init, monotonic

// ---------------- helpers ----------------
__device__ __forceinline__ void cp_async16(void* sdst, const void* gsrc) {
    uint32_t s = (uint32_t)__cvta_generic_to_shared(sdst);
    asm volatile("cp.async.cg.shared.global [%0], [%1], 16;\n" :: "r"(s), "l"(gsrc));
}
__device__ __forceinline__ void cp_commit() { asm volatile("cp.async.commit_group;\n"); }
template <int N> __device__ __forceinline__ void cp_wait() {
    asm volatile("cp.async.wait_group %0;\n" :: "n"(N));
}
__device__ __forceinline__ unsigned ld_acq(const unsigned* p) {
    unsigned v; asm volatile("ld.acquire.gpu.u32 %0, [%1];" : "=r"(v) : "l"(p)); return v;
}
__device__ __forceinline__ void mma16816(float* d,
    uint32_t a0, uint32_t a1, uint32_t a2, uint32_t a3, uint32_t b0, uint32_t b1)
{
    asm volatile(
        "mma.sync.aligned.m16n8k16.row.col.f32.f16.f16.f32 "
        "{%0,%1,%2,%3},{%4,%5,%6,%7},{%8,%9},{%0,%1,%2,%3};\n"
        : "+f"(d[0]), "+f"(d[1]), "+f"(d[2]), "+f"(d[3])
        : "r"(a0), "r"(a1), "r"(a2), "r"(a3), "r"(b0), "r"(b1));
}
__device__ __forceinline__ void ldsm4(uint32_t& a, uint32_t& b, uint32_t& c, uint32_t& d,
                                      uint32_t addr)
{
    asm volatile("ldmatrix.sync.aligned.m8n8.x4.shared.b16 {%0,%1,%2,%3}, [%4];"
        : "=r"(a), "=r"(b), "=r"(c), "=r"(d) : "r"(addr));
}
__device__ __forceinline__ float sigmoidf_(float z) { return 1.f / (1.f + __expf(-z)); }

// ---------------- packing ----------------
__global__ void pack_w_kernel(const float* __restrict__ src, int which, int K)
{
    f16* dst = (which == 0) ? g_Wi0p : (which == 1) ? g_Wh0p :
               (which == 2) ? g_Wi1p : g_Wh1p;
    int K4 = K >> 2;
    int total = G_ * K4;
    for (int id = blockIdx.x * blockDim.x + threadIdx.x; id < total;
         id += gridDim.x * blockDim.x) {
        int r = id / K4, k4 = (id - r * K4) * 4;
        int sr = (r & 3) * H_ + (r >> 2);
        float4 v = *(const float4*)&src[(size_t)sr * K + k4];
        __half2 a = {__float2half_rn(v.x), __float2half_rn(v.y)};
        __half2 b = {__float2half_rn(v.z), __float2half_rn(v.w)};
        *(uint2*)&dst[(size_t)r * K + k4] = make_uint2(*(uint32_t*)&a, *(uint32_t*)&b);
    }
}

__global__ void pack_x_kernel(const float* __restrict__ src)
{
    int total = TB_ * (D_ >> 2);
    for (int id = blockIdx.x * blockDim.x + threadIdx.x; id < total;
         id += gridDim.x * blockDim.x) {
        int r = id / (D_ >> 2), k4 = (id - r * (D_ >> 2)) * 4;
        float4 v = *(const float4*)&src[(size_t)r * D_ + k4];
        __half2 a = {__float2half_rn(v.x), __float2half_rn(v.y)};
        __half2 b = {__float2half_rn(v.z), __float2half_rn(v.w)};
        *(uint2*)&g_Xp[(size_t)r * D_ + k4] = make_uint2(*(uint32_t*)&a, *(uint32_t*)&b);
    }
}

__global__ void bias_kernel(const float* __restrict__ bi0, const float* __restrict__ bh0,
                            const float* __restrict__ bi1, const float* __restrict__ bh1)
{
    int r = blockIdx.x * blockDim.x + threadIdx.x;
    if (r < G_) {
        int sr = (r & 3) * H_ + (r >> 2);
        g_b0[r] = bi0[sr] + bh0[sr];
        g_b1[r] = bi1[sr] + bh1[sr];
    }
}

__global__ void init_state_kernel(const float* __restrict__ h0, const float* __restrict__ c0)
{
    int id = blockIdx.x * blockDim.x + threadIdx.x;
    if (id < 2 * B_ * H_) {
        int l = id / (B_ * H_);
        int b = (id / H_) % B_;
        int j = id % H_;
        float hv = h0[(b * 2 + l) * H_ + j];
        g_c0s[id] = c0[(b * 2 + l) * H_ + j];
        f16 hh = __float2half_rn(hv);
        if (l == 0) g_h0p[0][b * H_ + j] = hh;
        else        g_h1p[0][b * H_ + j] = hh;
    }
}

// ---------------- G0 GEMM: g_G0 = Xp @ Wi0p^T + b0 ----------------
#define GAS 72
__global__ __launch_bounds__(256) void gemm_kernel()
{
    extern __shared__ f16 sm[];
    const int AS = 128 * GAS;
    f16* sA = sm;
    f16* sB = sm + 3 * AS;
    uint32_t sA_u = (uint32_t)__cvta_generic_to_shared(sA);
    uint32_t sB_u = (uint32_t)__cvta_generic_to_shared(sB);

    const f16 *A = g_Xp, *B = g_Wi0p;
    const float* bias = g_b0;
    float* outp = g_G0;
    const int K = 512;

    int tid = threadIdx.x, w = tid >> 5, lane = tid & 31, g = lane >> 2, t4 = lane & 3;
    int wm = w & 1, wn = w >> 1;
    int m0 = blockIdx.y * 128, n0 = blockIdx.x * 128;
    const int NC = K / 64;

    int lr = lane & 15;
    int lcA = (lane >> 4) * 8;
    uint32_t aBase[4], bBase[2];
#pragma unroll
    for (int mt = 0; mt < 4; mt++)
        aBase[mt] = (uint32_t)(((wm * 64 + mt * 16 + lr) * GAS + lcA) * 2);
#pragma unroll
    for (int p = 0; p < 2; p++)
        bBase[p] = (uint32_t)(((wn * 32 + p * 16 + (lane & 7) + ((lane >> 4) & 1) * 8) * GAS
                               + ((lane >> 3) & 1) * 8) * 2);

    float acc[4][4][4];
#pragma unroll
    for (int a = 0; a < 4; a++)
#pragma unroll
        for (int b = 0; b < 4; b++)
#pragma unroll
            for (int c = 0; c < 4; c++) acc[a][b][c] = 0.f;

    auto issue = [&](int c) {
        int k0 = c * 64;
        int st = c % 3;
#pragma unroll
        for (int v = 0; v < 4; v++) {
            int idx = tid + v * 256;
            int r = idx >> 3, s = idx & 7;
            cp_async16(&sA[st * AS + r * GAS + s * 8], &A[(size_t)(m0 + r) * K + k0 + s * 8]);
        }
#pragma unroll
        for (int v = 0; v < 4; v++) {
            int idx = tid + v * 256;
            int r = idx >> 3, s = idx & 7;
            cp_async16(&sB[st * AS + r * GAS + s * 8], &B[(size_t)(n0 + r) * K + k0 + s * 8]);
        }
        cp_commit();
    };

    issue(0); issue(1);
    for (int c = 0; c < NC; c++) {
        if (c + 1 < NC) cp_wait<1>(); else cp_wait<0>();
        __syncthreads();
        if (c + 2 < NC) issue(c + 2);
        uint32_t stA = sA_u + (uint32_t)((c % 3) * AS * 2);
        uint32_t stB = sB_u + (uint32_t)((c % 3) * AS * 2);
#pragma unroll
        for (int kk = 0; kk < 4; kk++) {
            uint32_t kbb = (uint32_t)(kk * 32);
            uint32_t Aa[4][4], Bh[4][2];
#pragma unroll
            for (int mt = 0; mt < 4; mt++)
                ldsm4(Aa[mt][0], Aa[mt][1], Aa[mt][2], Aa[mt][3], stA + aBase[mt] + kbb);
#pragma unroll
            for (int p = 0; p < 2; p++)
                ldsm4(Bh[2 * p][0], Bh[2 * p][1], Bh[2 * p + 1][0], Bh[2 * p + 1][1],
                      stB + bBase[p] + kbb);
#pragma unroll
            for (int mt = 0; mt < 4; mt++)
#pragma unroll
                for (int nt = 0; nt < 4; nt++)
                    mma16816(acc[mt][nt], Aa[mt][0], Aa[mt][1], Aa[mt][2], Aa[mt][3], Bh[nt][0], Bh[nt][1]);
        }
    }

#pragma unroll
    for (int mt = 0; mt < 4; mt++)
#pragma unroll
        for (int nt = 0; nt < 4; nt++) {
            int row = m0 + wm * 64 + mt * 16 + g;
            int col = n0 + wn * 32 + nt * 8 + 2 * t4;
            float ba = bias[col], bb = bias[col + 1];
            *(float2*)&outp[(size_t)row * G_ + col] =
                make_float2(acc[mt][nt][0] + ba, acc[mt][nt][1] + bb);
            *(float2*)&outp[(size_t)(row + 8) * G_ + col] =
                make_float2(acc[mt][nt][2] + ba, acc[mt][nt][3] + bb);
        }
}

// ---------------- merged persistent wavefront kernel ----------------
// 128 CTAs x 256 threads, 257 super-steps. Super-step s:
//   layer0 step t=s   (s<256): z0 = G0[s] + keep0*(h0_{s-1} @ Wh0)
//   layer1 step t=s-1 (s>=1):  z1 = b1 + h0_{s-1}@Wi1 + keep1*(h1_{s-2} @ Wh1)
// Fused mainloop shares the A-stream h0_{s-1} between Wh0 (resident) and Wi1 (B-ring).
#define WSTR 1032
#define ASTR 136
#define ASTG (64 * ASTR)
#define BSTG (32 * ASTR)
#define ZBANK (64 * 36)

__global__ __launch_bounds__(256, 1) void merged_kernel(const int* __restrict__ reset,
                                                        float* __restrict__ out)
{
    extern __shared__ f16 smem[];
    f16* sW0 = smem;                       // Wh0 slice: 32 x WSTR
    f16* sW1 = smem + 32 * WSTR;           // Wh1 slice: 32 x WSTR
    f16* sA  = smem + 64 * WSTR;           // 3 x ASTG
    f16* sB  = sA + 3 * ASTG;              // 3 x BSTG (Wi1 ring)
    float* zs = (float*)(sB + 3 * BSTG);   // 2 banks x 64 x 36
    uint32_t sW0_u = (uint32_t)__cvta_generic_to_shared(sW0);
    uint32_t sW1_u = (uint32_t)__cvta_generic_to_shared(sW1);
    uint32_t sA_u  = (uint32_t)__cvta_generic_to_shared(sA);
    uint32_t sB_u  = (uint32_t)__cvta_generic_to_shared(sB);

    int tid = threadIdx.x, w = tid >> 5, lane = tid & 31, g = lane >> 2, t4 = lane & 3;
    int wk = w & 1, wn = (w >> 1) & 1, wm = w >> 2;
    int n0 = blockIdx.x * 32;
    unsigned gen0 = ld_acq(&g_bar_gen);

    // resident W slices
    for (int i = tid; i < 32 * 128; i += 256) {
        int r = i >> 7, sseg = i & 127;
        *(uint4*)&sW0[r * WSTR + sseg * 8] = *(const uint4*)&g_Wh0p[(size_t)(n0 + r) * H_ + sseg * 8];
        *(uint4*)&sW1[r * WSTR + sseg * 8] = *(const uint4*)&g_Wh1p[(size_t)(n0 + r) * H_ + sseg * 8];
    }

    // ldmatrix bases
    int lr = lane & 15;
    int lcA = (lane >> 4) * 8;
    uint32_t aBase[2];
    aBase[0] = (uint32_t)(((wm * 32 + 0 + lr) * ASTR + lcA) * 2);
    aBase[1] = (uint32_t)(((wm * 32 + 16 + lr) * ASTR + lcA) * 2);
    uint32_t wBase[2], bBaseS[2];
#pragma unroll
    for (int nt = 0; nt < 2; nt++) {
        wBase[nt]  = (uint32_t)(((wn * 16 + nt * 8 + (lane & 7)) * WSTR
                                 + ((lane >> 3) & 1) * 8 + ((lane >> 4) & 1) * 16) * 2);
        bBaseS[nt] = (uint32_t)(((wn * 16 + nt * 8 + (lane & 7)) * ASTR
                                 + ((lane >> 3) & 1) * 8 + ((lane >> 4) & 1) * 16) * 2);
    }

    int bb = tid >> 3, jl = tid & 7, j = blockIdx.x * 8 + jl;
    int bb2 = (tid + 256) >> 3;
    int wrow[4] = { wm * 32 + g, wm * 32 + 8 + g, wm * 32 + 16 + g, wm * 32 + 24 + g };

    float c0r[2], c1r[2];
    c0r[0] = g_c0s[(0 * B_ + bb) * H_ + j];
    c0r[1] = g_c0s[(0 * B_ + bb2) * H_ + j];
    c1r[0] = g_c0s[(1 * B_ + bb) * H_ + j];
    c1r[1] = g_c0s[(1 * B_ + bb2) * H_ + j];

    float4 b1v = *(const float4*)&g_b1[n0 + 4 * jl];

    float4 gp[2]; float rst0[2], rst1[2], kw[4];
    gp[0] = *(const float4*)&g_G0[(size_t)bb * G_ + n0 + 4 * jl];
    gp[1] = *(const float4*)&g_G0[(size_t)bb2 * G_ + n0 + 4 * jl];
    rst0[0] = (float)reset[bb];
    rst0[1] = (float)reset[bb2];
    rst1[0] = rst1[1] = 0.f;
    kw[0] = kw[1] = kw[2] = kw[3] = 1.f;
    __syncthreads();

    for (int s = 0; s <= T_; s++) {
        const f16* A0 = g_h0p[s & 1];          // h0_{s-1}
        const f16* A1 = g_h1p[(s + 1) & 1];    // h1_{s-2}

        float acc0[2][2][4], accWi[2][2][4];
#pragma unroll
        for (int a = 0; a < 2; a++)
#pragma unroll
            for (int b = 0; b < 2; b++)
#pragma unroll
                for (int c = 0; c < 4; c++) { acc0[a][b][c] = 0.f; accWi[a][b][c] = 0.f; }

        // ---- fused mainloop: A=h0prev vs (Wh0 resident, Wi1 ring) ----
        auto issueF = [&](int c) {
            int k0 = c * 128, st = c % 3;
#pragma unroll
            for (int v = 0; v < 4; v++) {
                int idx = tid + v * 256;
                int r = idx >> 4, sseg = idx & 15;
                cp_async16(&sA[st * ASTG + r * ASTR + sseg * 8], &A0[(size_t)r * H_ + k0 + sseg * 8]);
            }
#pragma unroll
            for (int v = 0; v < 2; v++) {
                int idx = tid + v * 256;
                int r = idx >> 4, sseg = idx & 15;
                cp_async16(&sB[st * BSTG + r * ASTR + sseg * 8],
                           &g_Wi1p[(size_t)(n0 + r) * H_ + k0 + sseg * 8]);
            }
            cp_commit();
        };

        issueF(0); issueF(1);
        for (int c = 0; c < 8; c++) {
            if (c + 1 < 8) cp_wait<1>(); else cp_wait<0>();
            __syncthreads();
            if (c + 2 < 8) issueF(c + 2);
            uint32_t stA = sA_u + (uint32_t)((c % 3) * ASTG * 2);
            uint32_t stB = sB_u + (uint32_t)((c % 3) * BSTG * 2);
            uint32_t wOffC = (uint32_t)(c * 128 * 2);
#pragma unroll
            for (int kpi = 0; kpi < 2; kpi++) {
                int kp = kpi * 2 + wk;
                uint32_t kpb = (uint32_t)(kp * 64);
                uint32_t Bq0[2][4], BqW[2][4];
#pragma unroll
                for (int nt = 0; nt < 2; nt++) {
                    ldsm4(Bq0[nt][0], Bq0[nt][1], Bq0[nt][2], Bq0[nt][3],
                          sW0_u + wBase[nt] + wOffC + kpb);
                    ldsm4(BqW[nt][0], BqW[nt][1], BqW[nt][2], BqW[nt][3],
                          stB + bBaseS[nt] + kpb);
                }
#pragma unroll
                for (int h = 0; h < 2; h++) {
                    uint32_t kbb = kpb + (uint32_t)(h * 32);
                    uint32_t Aa[2][4];
#pragma unroll
                    for (int mt = 0; mt < 2; mt++)
                        ldsm4(Aa[mt][0], Aa[mt][1], Aa[mt][2], Aa[mt][3], stA + aBase[mt] + kbb);
#pragma unroll
                    for (int mt = 0; mt < 2; mt++)
#pragma unroll
                        for (int nt = 0; nt < 2; nt++) {
                            mma16816(acc0[mt][nt], Aa[mt][0], Aa[mt][1], Aa[mt][2], Aa[mt][3],
                                     Bq0[nt][h * 2], Bq0[nt][h * 2 + 1]);
                            mma16816(accWi[mt][nt], Aa[mt][0], Aa[mt][1], Aa[mt][2], Aa[mt][3],
                                     BqW[nt][h * 2], BqW[nt][h * 2 + 1]);
                        }
                }
            }
        }

        // layer0 partials -> zs (this wk's bank)
        {
            float* zb = zs + wk * ZBANK;
#pragma unroll
            for (int mt = 0; mt < 2; mt++)
#pragma unroll
                for (int nt = 0; nt < 2; nt++) {
                    int r0 = wm * 32 + mt * 16 + g;
                    int c0 = wn * 16 + nt * 8 + 2 * t4;
                    zb[r0 * 36 + c0]     = acc0[mt][nt][0];
                    zb[r0 * 36 + c0 + 1] = acc0[mt][nt][1];
                    zb[(r0 + 8) * 36 + c0]     = acc0[mt][nt][2];
                    zb[(r0 + 8) * 36 + c0 + 1] = acc0[mt][nt][3];
                }
        }
        __syncthreads();

        // ---- issue Wh1 chunks early (A = h1_{s-2}) ----
        auto issueH = [&](int c) {
            int k0 = c * 128, st = c % 3;
#pragma unroll
            for (int v = 0; v < 4; v++) {
                int idx = tid + v * 256;
                int r = idx >> 4, sseg = idx & 15;
                cp_async16(&sA[st * ASTG + r * ASTR + sseg * 8], &A1[(size_t)r * H_ + k0 + sseg * 8]);
            }
            cp_commit();
        };
        if (s >= 1) { issueH(0); issueH(1); }

        // ---- tail0: layer0 activation, store h0_s ----
        if (s < T_) {
#pragma unroll
            for (int it = 0; it < 2; it++) {
                int b = it ? bb2 : bb;
                float keep = 1.0f - rst0[it];
                int zi_i = b * 36 + 4 * jl;
                float zi = gp[it].x + keep * (zs[zi_i + 0] + zs[ZBANK + zi_i + 0]);
                float zf = gp[it].y + keep * (zs[zi_i + 1] + zs[ZBANK + zi_i + 1]);
                float zg = gp[it].z + keep * (zs[zi_i + 2] + zs[ZBANK + zi_i + 2]);
                float zo = gp[it].w + keep * (zs[zi_i + 3] + zs[ZBANK + zi_i + 3]);
                float cn = sigmoidf_(zf) * keep * c0r[it] + sigmoidf_(zi) * tanhf(zg);
                float hn = sigmoidf_(zo) * tanhf(cn);
                c0r[it] = cn;
                g_h0p[(s + 1) & 1][b * H_ + j] = __float2half_rn(hn);
                if (s == T_ - 1) {
                    out[OUTS_ + (b * 2 + 0) * H_ + j] = hn;
                    out[OUTS_ + 2 * B_ * H_ + (b * 2 + 0) * H_ + j] = cn;
                }
            }
        }

        float hn_s[2], cn_s[2];
        if (s >= 1) {
            // ---- Wh1 mainloop ----
            float accWh[2][2][4];
#pragma unroll
            for (int a = 0; a < 2; a++)
#pragma unroll
                for (int b = 0; b < 2; b++)
#pragma unroll
                    for (int c = 0; c < 4; c++) accWh[a][b][c] = 0.f;

            for (int c = 0; c < 8; c++) {
                if (c + 1 < 8) cp_wait<1>(); else cp_wait<0>();
                __syncthreads();
                if (c + 2 < 8) issueH(c + 2);
                uint32_t stA = sA_u + (uint32_t)((c % 3) * ASTG * 2);
                uint32_t wOffC = (uint32_t)(c * 128 * 2);
#pragma unroll
                for (int kpi = 0; kpi < 2; kpi++) {
                    int kp = kpi * 2 + wk;
                    uint32_t kpb = (uint32_t)(kp * 64);
                    uint32_t Bq1[2][4];
#pragma unroll
                    for (int nt = 0; nt < 2; nt++)
                        ldsm4(Bq1[nt][0], Bq1[nt][1], Bq1[nt][2], Bq1[nt][3],
                              sW1_u + wBase[nt] + wOffC + kpb);
#pragma unroll
                    for (int h = 0; h < 2; h++) {
                        uint32_t kbb = kpb + (uint32_t)(h * 32);
                        uint32_t Aa[2][4];
#pragma unroll
                        for (int mt = 0; mt < 2; mt++)
                            ldsm4(Aa[mt][0], Aa[mt][1], Aa[mt][2], Aa[mt][3], stA + aBase[mt] + kbb);
#pragma unroll
                        for (int mt = 0; mt < 2; mt++)
#pragma unroll
                            for (int nt = 0; nt < 2; nt++)
                                mma16816(accWh[mt][nt], Aa[mt][0], Aa[mt][1], Aa[mt][2], Aa[mt][3],
                                         Bq1[nt][h * 2], Bq1[nt][h * 2 + 1]);
                    }
                }
            }

            // layer1 partials: zs = kw*accWh + accWi (writer-side keep, exact since kw in {0,1})
            {
                float* zb = zs + wk * ZBANK;
#pragma unroll
                for (int mt = 0; mt < 2; mt++)
#pragma unroll
                    for (int nt = 0; nt < 2; nt++) {
                        int r0 = wm * 32 + mt * 16 + g;
                        int c0 = wn * 16 + nt * 8 + 2 * t4;
                        float k0f = kw[mt * 2 + 0], k1f = kw[mt * 2 + 1];
                        zb[r0 * 36 + c0]     = k0f * accWh[mt][nt][0] + accWi[mt][nt][0];
                        zb[r0 * 36 + c0 + 1] = k0f * accWh[mt][nt][1] + accWi[mt][nt][1];
                        zb[(r0 + 8) * 36 + c0]     = k1f * accWh[mt][nt][2] + accWi[mt][nt][2];
                        zb[(r0 + 8) * 36 + c0 + 1] = k1f * accWh[mt][nt][3] + accWi[mt][nt][3];
                    }
            }
            __syncthreads();

            // ---- tail1: layer1 activation, store h1_{s-1} ----
#pragma unroll
            for (int it = 0; it < 2; it++) {
                int b = it ? bb2 : bb;
                float keep = 1.0f - rst1[it];
                int zi_i = b * 36 + 4 * jl;
                float zi = b1v.x + (zs[zi_i + 0] + zs[ZBANK + zi_i + 0]);
                float zf = b1v.y + (zs[zi_i + 1] + zs[ZBANK + zi_i + 1]);
                float zg = b1v.z + (zs[zi_i + 2] + zs[ZBANK + zi_i + 2]);
                float zo = b1v.w + (zs[zi_i + 3] + zs[ZBANK + zi_i + 3]);
                float cn = sigmoidf_(zf) * keep * c1r[it] + sigmoidf_(zi) * tanhf(zg);
                float hn = sigmoidf_(zo) * tanhf(cn);
                c1r[it] = cn; cn_s[it] = cn; hn_s[it] = hn;
                g_h1p[s & 1][b * H_ + j] = __float2half_rn(hn);
                if (s == T_) {
                    out[OUTS_ + (b * 2 + 1) * H_ + j] = hn;
                    out[OUTS_ + 2 * B_ * H_ + (b * 2 + 1) * H_ + j] = cn;
                }
            }
        }

        // ---- barrier arrive ----
        __syncthreads();
        if (tid == 0) {
            __threadfence();
            unsigned grp = (unsigned)blockIdx.x >> 4;
            if (atomicAdd(&g_bar_grp[grp], 1u) == 15u) {
                g_bar_grp[grp] = 0u;
                if (atomicAdd(&g_bar_root, 1u) == 7u) {
                    g_bar_root = 0u;
                    __threadfence();
                    g_bar_gen = gen0 + s + 1;
                }
            }
        }

        // ---- overlap: output stores + prefetch for super-step s+1 ----
        if (s >= 1) {
            int t1 = s - 1;
#pragma unroll
            for (int it = 0; it < 2; it++) {
                int b = it ? bb2 : bb;
                out[(size_t)t1 * B_ * H_ + b * H_ + j] = hn_s[it];
            }
        }
        if (s + 1 <= T_) {
            rst1[0] = rst0[0]; rst1[1] = rst0[1];
            if (s + 1 < T_) {
                gp[0] = *(const float4*)&g_G0[((size_t)(s + 1) * B_ + bb) * G_ + n0 + 4 * jl];
                gp[1] = *(const float4*)&g_G0[((size_t)(s + 1) * B_ + bb2) * G_ + n0 + 4 * jl];
                rst0[0] = (float)reset[(s + 1) * B_ + bb];
                rst0[1] = (float)reset[(s + 1) * B_ + bb2];
            }
#pragma unroll
            for (int i = 0; i < 4; i++)
                kw[i] = 1.0f - (float)reset[s * B_ + wrow[i]];
        }

        if (tid == 0) {
            while (ld_acq(&g_bar_gen) < gen0 + s + 1) { }
        }
        __syncthreads();
    }
}

// ---------------- launch ----------------
extern "C" void kernel_launch(void* const* d_in, const int* in_sizes, int n_in,
                              void* d_out, int out_size)
{
    (void)in_sizes; (void)n_in; (void)out_size;
    const float* input = (const float*)d_in[0];
    const int*   reset = (const int*)d_in[1];
    const float* h0    = (const float*)d_in[2];
    const float* c0    = (const float*)d_in[3];
    const float* Wi0   = (const float*)d_in[4];
    const float* Wh0   = (const float*)d_in[5];
    const float* bi0   = (const float*)d_in[6];
    const float* bh0   = (const float*)d_in[7];
    const float* Wi1   = (const float*)d_in[8];
    const float* Wh1   = (const float*)d_in[9];
    const float* bi1   = (const float*)d_in[10];
    const float* bh1   = (const float*)d_in[11];
    float* out = (float*)d_out;

    const int GEMM_SMEM   = 6 * 128 * GAS * 2;                                   // 110592 B
    const int MERGED_SMEM = (64 * WSTR + 3 * ASTG + 3 * BSTG) * 2 + 2 * ZBANK * 4; // 228864 B
    cudaFuncSetAttribute(gemm_kernel,   cudaFuncAttributeMaxDynamicSharedMemorySize, GEMM_SMEM);
    cudaFuncSetAttribute(merged_kernel, cudaFuncAttributeMaxDynamicSharedMemorySize, MERGED_SMEM);

    pack_w_kernel<<<1024, 256>>>(Wi0, 0, D_);
    pack_w_kernel<<<1024, 256>>>(Wh0, 1, H_);
    pack_w_kernel<<<1024, 256>>>(Wi1, 2, H_);
    pack_w_kernel<<<1024, 256>>>(Wh1, 3, H_);
    pack_x_kernel<<<1024, 256>>>(input);
    bias_kernel<<<16, 256>>>(bi0, bh0, bi1, bh1);
    init_state_kernel<<<512, 256>>>(h0, c0);

    gemm_kernel<<<dim3(32, 128), 256, GEMM_SMEM>>>();       // G0
    merged_kernel<<<NB_, 256, MERGED_SMEM>>>(reset, out);   // both layers, wavefront
}